// round 14
// baseline (speedup 1.0000x reference)
#include <cuda_runtime.h>
#include <cuda_bf16.h>
#include <cstdint>
#include <math.h>

#define T_DIM 512
#define B_DIM 256
#define H_DIM 256
#define H3    768
#define M_TOT (T_DIM * B_DIM)
#define NCTA2 296   // persistent wave kernel: 2 CTAs per SM
#define FINE_MAX 2368   // waves with n <= this use 16-row fine tiles

// Precomputed input gates gi = ins @ Wi + bi : [T*B][3H] fp32 (402 MB)
__device__ float g_gi[(size_t)M_TOT * H3];
// Pre-split weights (bf16 hi/lo), row-major [K][3H]
__device__ __nv_bfloat16 g_wi_h[H_DIM * H3], g_wi_l[H_DIM * H3];
__device__ __nv_bfloat16 g_wh_h[H_DIM * H3], g_wh_l[H_DIM * H3];
// Scheduling: wave items (non-reset rows) + flat items (reset rows, gh==0)
__device__ int g_wave_cnt[T_DIM];
__device__ int g_items[M_TOT];         // item = (t<<8)|b, grouped by depth
__device__ int g_flat_cnt;
__device__ int g_flat_items[M_TOT];
// Tree grid-barrier state (re-initialized by setup each replay)
__device__ unsigned g_bar_grp[8 * 32];   // group counters, 128B apart
__device__ unsigned g_bar_root;
__device__ volatile unsigned g_bar_sense;

// ---------------------------------------------------------------------------
// PTX helpers
// ---------------------------------------------------------------------------
__device__ __forceinline__ uint32_t smem_u32(const void* p) {
    return (uint32_t)__cvta_generic_to_shared(p);
}
__device__ __forceinline__ void ldsm_x4(uint32_t* r, uint32_t a) {
    asm volatile("ldmatrix.sync.aligned.m8n8.x4.shared.b16 {%0,%1,%2,%3}, [%4];"
                 : "=r"(r[0]), "=r"(r[1]), "=r"(r[2]), "=r"(r[3]) : "r"(a));
}
__device__ __forceinline__ void ldsm_x4t(uint32_t* r, uint32_t a) {
    asm volatile("ldmatrix.sync.aligned.m8n8.x4.trans.shared.b16 {%0,%1,%2,%3}, [%4];"
                 : "=r"(r[0]), "=r"(r[1]), "=r"(r[2]), "=r"(r[3]) : "r"(a));
}
__device__ __forceinline__ void ldsm_x2t(uint32_t* r, uint32_t a) {
    asm volatile("ldmatrix.sync.aligned.m8n8.x2.trans.shared.b16 {%0,%1}, [%2];"
                 : "=r"(r[0]), "=r"(r[1]) : "r"(a));
}
__device__ __forceinline__ void mma_bf16(float* c, const uint32_t* a, const uint32_t* b) {
    asm volatile("mma.sync.aligned.m16n8k16.row.col.f32.bf16.bf16.f32 "
                 "{%0,%1,%2,%3}, {%4,%5,%6,%7}, {%8,%9}, {%0,%1,%2,%3};"
                 : "+f"(c[0]), "+f"(c[1]), "+f"(c[2]), "+f"(c[3])
                 : "r"(a[0]), "r"(a[1]), "r"(a[2]), "r"(a[3]),
                   "r"(b[0]), "r"(b[1]));
}
__device__ __forceinline__ void split4(__nv_bfloat16* dh, __nv_bfloat16* dl, float4 v) {
    float vv[4] = { v.x, v.y, v.z, v.w };
    __nv_bfloat16 h[4], l[4];
    #pragma unroll
    for (int i = 0; i < 4; i++) {
        h[i] = __float2bfloat16(vv[i]);
        l[i] = __float2bfloat16(vv[i] - __bfloat162float(h[i]));
    }
    *(__nv_bfloat162*)&dh[0] = __nv_bfloat162(h[0], h[1]);
    *(__nv_bfloat162*)&dh[2] = __nv_bfloat162(h[2], h[3]);
    *(__nv_bfloat162*)&dl[0] = __nv_bfloat162(l[0], l[1]);
    *(__nv_bfloat162*)&dl[2] = __nv_bfloat162(l[2], l[3]);
}
// cp.async (LDGSTS): 16B global->shared, no register staging
__device__ __forceinline__ void cp_async16(void* smem_dst, const void* gmem_src) {
    asm volatile("cp.async.cg.shared.global [%0], [%1], 16;"
                 :: "r"(smem_u32(smem_dst)), "l"(gmem_src) : "memory");
}
__device__ __forceinline__ void cp_commit() {
    asm volatile("cp.async.commit_group;" ::: "memory");
}
__device__ __forceinline__ void cp_wait_all() {
    asm volatile("cp.async.wait_group 0;" ::: "memory");
}
// Fast transcendentals via MUFU (ex2.approx / rcp.approx).
// sigmoid(x) = rcp(1 + 2^(-x*log2e)); tanh(x) = 1 - 2*rcp(1 + 2^(2x*log2e))
__device__ __forceinline__ float fast_sigmoid(float x) {
    float e, r;
    asm("ex2.approx.f32 %0, %1;" : "=f"(e) : "f"(-1.4426950408889634f * x));
    asm("rcp.approx.f32 %0, %1;" : "=f"(r) : "f"(1.0f + e));
    return r;
}
__device__ __forceinline__ float fast_tanh(float x) {
    float e, r;
    asm("ex2.approx.f32 %0, %1;" : "=f"(e) : "f"(2.8853900817779268f * x));
    asm("rcp.approx.f32 %0, %1;" : "=f"(r) : "f"(1.0f + e));
    return 1.0f - 2.0f * r;
}

// ---------------------------------------------------------------------------
// Kernel 0: setup. Blocks 0..767: split Wi/Wh to bf16 hi/lo.
// Block 768: build wave/flat schedule from resets + reset barrier state.
// ---------------------------------------------------------------------------
__global__ __launch_bounds__(256) void setup(const float* __restrict__ Wi,
                                             const float* __restrict__ Wh,
                                             const int* __restrict__ resets) {
    const int tid = threadIdx.x;
    if (blockIdx.x < 768) {
        const int i = blockIdx.x * 256 + tid;
        float v = Wi[i];
        __nv_bfloat16 h = __float2bfloat16(v);
        g_wi_h[i] = h;
        g_wi_l[i] = __float2bfloat16(v - __bfloat162float(h));
        v = Wh[i];
        h = __float2bfloat16(v);
        g_wh_h[i] = h;
        g_wh_l[i] = __float2bfloat16(v - __bfloat162float(h));
        return;
    }
    // schedule-building block
    __shared__ int s_cnt[T_DIM + 1];
    __shared__ int s_cur[T_DIM + 1];
    for (int i = tid; i < T_DIM + 1; i += 256) s_cnt[i] = 0;
    if (tid < 8 * 32) g_bar_grp[tid] = 0;
    if (tid == 0) { g_bar_root = 0; g_bar_sense = 0; }
    __syncthreads();

    const int b = tid;
    {   // Pass 1: counts
        int d = 0;
        bool prev_reset = true;
        for (int t = 0; t < T_DIM; t++) {
            const int rst = resets[t * B_DIM + b];
            int key;
            if (rst) { key = T_DIM; prev_reset = true; }
            else     { d = prev_reset ? 0 : d + 1; key = d; prev_reset = false; }
            const unsigned mask = __match_any_sync(0xffffffffu, key);
            const int leader = __ffs(mask) - 1;
            if ((tid & 31) == leader) atomicAdd(&s_cnt[key], __popc(mask));
        }
    }
    __syncthreads();
    if (tid == 0) {
        int acc = 0;
        for (int i = 0; i < T_DIM; i++) {
            const int c = s_cnt[i];
            g_wave_cnt[i] = c;
            s_cur[i] = acc;
            acc += c;
        }
        g_flat_cnt = s_cnt[T_DIM];
        s_cur[T_DIM] = 0;
    }
    __syncthreads();
    {   // Pass 2: fill lists
        int d = 0;
        bool prev_reset = true;
        for (int t = 0; t < T_DIM; t++) {
            const int rst = resets[t * B_DIM + b];
            int key;
            if (rst) { key = T_DIM; prev_reset = true; }
            else     { d = prev_reset ? 0 : d + 1; key = d; prev_reset = false; }
            const unsigned mask = __match_any_sync(0xffffffffu, key);
            const int leader = __ffs(mask) - 1;
            int base = 0;
            if ((tid & 31) == leader) base = atomicAdd(&s_cur[key], __popc(mask));
            base = __shfl_sync(0xffffffffu, base, leader);
            const int rank = __popc(mask & ((1u << (tid & 31)) - 1u));
            const int item = (t << 8) | b;
            if (key == T_DIM) g_flat_items[base + rank] = item;
            else              g_items[base + rank]      = item;
        }
    }
}

// ---------------------------------------------------------------------------
// Kernel 1: GI = ins @ Wi + bi — mma.sync, double-buffered, cp.async B tiles.
// BM=128, BN=128, BK=32. 8 warps: 4(M) x 2(N); warp tile m32 x n64.
// ---------------------------------------------------------------------------
#define LDA 40
#define LDBg 136
#define GI_A_ST (128 * LDA)
#define GI_B_ST (32 * LDBg)
#define GI_SMEM_BYTES ((2 * GI_A_ST * 2 + 2 * GI_B_ST * 2) * 2)
__global__ __launch_bounds__(256, 2) void gi_gemm(const float* __restrict__ A,
                                                  const float* __restrict__ bi) {
    extern __shared__ __nv_bfloat16 sm[];
    __nv_bfloat16* Ah = sm;
    __nv_bfloat16* Al = Ah + 2 * GI_A_ST;
    __nv_bfloat16* Bh = Al + 2 * GI_A_ST;
    __nv_bfloat16* Bl = Bh + 2 * GI_B_ST;

    const int tid = threadIdx.x;
    const int wid = tid >> 5, lane = tid & 31;
    const int m0 = blockIdx.y * 128, n0 = blockIdx.x * 128;
    const int wm = (wid >> 1) * 32, wn = (wid & 1) * 64;
    const int g = lane >> 2, tg = lane & 3;

    const int arow = tid >> 1, acb = (tid & 1) * 16;
    const int brow = tid >> 3, bcb = (tid & 7) * 16;

    float acc[2][8][4];
    #pragma unroll
    for (int mb = 0; mb < 2; mb++)
        #pragma unroll
        for (int nb = 0; nb < 8; nb++)
            #pragma unroll
            for (int q = 0; q < 4; q++) acc[mb][nb][q] = 0.f;

    float4 pa[4];
    // preamble: B via cp.async into stage 0, A via regs -> split store stage 0
    {
        const size_t src = (size_t)brow * H3 + n0 + bcb;
        cp_async16(&Bh[brow * LDBg + bcb],     &g_wi_h[src]);
        cp_async16(&Bh[brow * LDBg + bcb + 8], &g_wi_h[src + 8]);
        cp_async16(&Bl[brow * LDBg + bcb],     &g_wi_l[src]);
        cp_async16(&Bl[brow * LDBg + bcb + 8], &g_wi_l[src + 8]);
        cp_commit();
    }
    #pragma unroll
    for (int q = 0; q < 4; q++)
        pa[q] = *(const float4*)&A[(size_t)(m0 + arow) * H_DIM + acb + q * 4];
    #pragma unroll
    for (int q = 0; q < 4; q++)
        split4(&Ah[arow * LDA + acb + q * 4], &Al[arow * LDA + acb + q * 4], pa[q]);

    int st = 0;
    for (int k0 = 0; k0 < H_DIM; k0 += 32) {
        cp_wait_all();          // B(st) landed (own-thread) ...
        __syncthreads();        // ... and visible to all; A(st) visible; ns free
        const bool more = (k0 + 32 < H_DIM);
        if (more) {
            const int ns = st ^ 1;
            const size_t src = (size_t)(k0 + 32 + brow) * H3 + n0 + bcb;
            cp_async16(&Bh[ns * GI_B_ST + brow * LDBg + bcb],     &g_wi_h[src]);
            cp_async16(&Bh[ns * GI_B_ST + brow * LDBg + bcb + 8], &g_wi_h[src + 8]);
            cp_async16(&Bl[ns * GI_B_ST + brow * LDBg + bcb],     &g_wi_l[src]);
            cp_async16(&Bl[ns * GI_B_ST + brow * LDBg + bcb + 8], &g_wi_l[src + 8]);
            cp_commit();
            #pragma unroll
            for (int q = 0; q < 4; q++)
                pa[q] = *(const float4*)&A[(size_t)(m0 + arow) * H_DIM + k0 + 32 + acb + q * 4];
        }

        const __nv_bfloat16* cAh = Ah + st * GI_A_ST;
        const __nv_bfloat16* cAl = Al + st * GI_A_ST;
        const __nv_bfloat16* cBh = Bh + st * GI_B_ST;
        const __nv_bfloat16* cBl = Bl + st * GI_B_ST;
        #pragma unroll
        for (int ks = 0; ks < 2; ks++) {
            const int kk = ks * 16;
            uint32_t afh[2][4], afl[2][4];
            #pragma unroll
            for (int mb = 0; mb < 2; mb++) {
                const int r = wm + mb * 16 + (lane & 15);
                const int c = kk + (lane >> 4) * 8;
                ldsm_x4(afh[mb], smem_u32(&cAh[r * LDA + c]));
                ldsm_x4(afl[mb], smem_u32(&cAl[r * LDA + c]));
            }
            #pragma unroll
            for (int nb2 = 0; nb2 < 4; nb2++) {
                uint32_t bh4[4], bl4[4];
                const int br2 = kk + (lane & 15);
                const int bc2 = wn + nb2 * 16 + (lane >> 4) * 8;
                ldsm_x4t(bh4, smem_u32(&cBh[br2 * LDBg + bc2]));
                ldsm_x4t(bl4, smem_u32(&cBl[br2 * LDBg + bc2]));
                #pragma unroll
                for (int hh = 0; hh < 2; hh++) {
                    #pragma unroll
                    for (int mb = 0; mb < 2; mb++) {
                        mma_bf16(acc[mb][nb2 * 2 + hh], afh[mb], &bh4[hh * 2]);
                        mma_bf16(acc[mb][nb2 * 2 + hh], afh[mb], &bl4[hh * 2]);
                        mma_bf16(acc[mb][nb2 * 2 + hh], afl[mb], &bh4[hh * 2]);
                    }
                }
            }
        }

        if (more) {
            const int ns = st ^ 1;
            #pragma unroll
            for (int q = 0; q < 4; q++)
                split4(&Ah[ns * GI_A_ST + arow * LDA + acb + q * 4],
                       &Al[ns * GI_A_ST + arow * LDA + acb + q * 4], pa[q]);
        }
        st ^= 1;
    }

    #pragma unroll
    for (int nb = 0; nb < 8; nb++) {
        const int col = n0 + wn + nb * 8 + 2 * tg;
        const float2 bb = *(const float2*)&bi[col];
        #pragma unroll
        for (int mb = 0; mb < 2; mb++) {
            const int row = m0 + wm + mb * 16 + g;
            float2 o0 = { acc[mb][nb][0] + bb.x, acc[mb][nb][1] + bb.y };
            float2 o1 = { acc[mb][nb][2] + bb.x, acc[mb][nb][3] + bb.y };
            *(float2*)&g_gi[(size_t)row * H3 + col]       = o0;
            *(float2*)&g_gi[(size_t)(row + 8) * H3 + col] = o1;
        }
    }
}

// ---------------------------------------------------------------------------
// Kernel 2b: flat rows (reset -> h_prev==0, gh==0). Pure pointwise, DRAM-bound.
// ---------------------------------------------------------------------------
__global__ __launch_bounds__(256) void flat_reset(const float* __restrict__ bhn,
                                                  float* __restrict__ out) {
    const int nit = g_flat_cnt;
    const int total = nit * 64;
    for (int idx = blockIdx.x * 256 + threadIdx.x; idx < total;
         idx += gridDim.x * 256) {
        const int it = idx >> 6;
        const int j  = (idx & 63) * 4;
        const int item = g_flat_items[it];
        const float* gi = g_gi + (size_t)item * H3 + j;
        const float4 gr = *(const float4*)gi;
        const float4 gz = *(const float4*)(gi + H_DIM);
        const float4 gn = *(const float4*)(gi + 2 * H_DIM);
        const float4 bn = *(const float4*)&bhn[j];
        const float grv[4] = { gr.x, gr.y, gr.z, gr.w };
        const float gzv[4] = { gz.x, gz.y, gz.z, gz.w };
        const float gnv[4] = { gn.x, gn.y, gn.z, gn.w };
        const float bnv[4] = { bn.x, bn.y, bn.z, bn.w };
        float o[4];
        #pragma unroll
        for (int c = 0; c < 4; c++) {
            const float r  = fast_sigmoid(grv[c]);
            const float z  = fast_sigmoid(gzv[c]);
            const float nn = fast_tanh(gnv[c] + r * bnv[c]);
            o[c] = (1.f - z) * nn;
        }
        *(float4*)(out + (size_t)item * H_DIM + j) =
            make_float4(o[0], o[1], o[2], o[3]);
    }
}

// ---------------------------------------------------------------------------
// Tree grid barrier: 8 groups (gridDim.x divisible by 8) + root.
// ---------------------------------------------------------------------------
__device__ __forceinline__ void grid_barrier(unsigned& sense) {
    __syncthreads();
    sense ^= 1u;
    if (threadIdx.x == 0) {
        __threadfence();
        const unsigned grp = blockIdx.x & 7;
        const unsigned gsize = gridDim.x >> 3;
        const unsigned pos = atomicAdd(&g_bar_grp[grp * 32], 1u);
        if (pos == gsize - 1) {
            atomicExch(&g_bar_grp[grp * 32], 0u);
            const unsigned rpos = atomicAdd(&g_bar_root, 1u);
            if (rpos == 7) {
                atomicExch(&g_bar_root, 0u);
                __threadfence();
                g_bar_sense = sense;
            }
        }
        while (g_bar_sense != sense) { __nanosleep(32); }
        __threadfence();
    }
    __syncthreads();
}

// ---------------------------------------------------------------------------
// Kernel 3: wave GEMM scan — mma.sync, cp.async, 2 CTAs/SM.
// Coarse path: 64-row tiles, double-buffered (fat waves).
// Fine path:   16-row tiles, single-stage (tail waves, n <= FINE_MAX).
// ---------------------------------------------------------------------------
#define LDBw 200
#define WV_A_ST (64 * LDA)
#define WV_B_ST (32 * LDBw)
#define WV_SMEM_BYTES ((2 * WV_A_ST * 2 + 2 * WV_B_ST * 2) * 2)
__global__ __launch_bounds__(256, 2) void gru_waves(
    const float* __restrict__ carry,    // [B,H]
    const float* __restrict__ bhn,      // [H]
    float*       __restrict__ out)      // [T,B,H]
{
    extern __shared__ __nv_bfloat16 sm[];
    __nv_bfloat16* Ah = sm;
    __nv_bfloat16* Al = Ah + 2 * WV_A_ST;
    __nv_bfloat16* Bh = Al + 2 * WV_A_ST;
    __nv_bfloat16* Bl = Bh + 2 * WV_B_ST;
    __shared__ const float* s_ptr[64];
    __shared__ int s_item[64];

    const int tid = threadIdx.x;
    const int wid = tid >> 5, lane = tid & 31;
    const int wm = (wid >> 2) * 32, wj = (wid & 3) * 16;
    const int g = lane >> 2, tg = lane & 3;

    const int garow = tid >> 2, gacb = (tid & 3) * 8;   // A: 64 x 32
    const int gbrow = tid >> 3, gbcb = (tid & 7) * 8;   // B per gate: 32 x 64

    unsigned sense = 0;
    int off = 0;

    for (int w = 0; w < T_DIM; w++) {
        const int n = g_wave_cnt[w];
        if (n == 0) break;

        if (n > FINE_MAX) {
            // ----------------- COARSE PATH (64-row tiles) -----------------
            const int ntiles = ((n + 63) >> 6) << 2;
            for (int tile = blockIdx.x; tile < ntiles; tile += gridDim.x) {
                const int m0 = (tile >> 2) << 6;
                const int j0 = (tile & 3) << 6;

                __syncthreads();
                if (tid < 64) {
                    const int m = m0 + tid;
                    const float* p = nullptr;
                    int item = 0;
                    if (m < n) {
                        item = g_items[off + m];
                        const int t = item >> 8;
                        const int b = item & 255;
                        p = (t == 0) ? (carry + (size_t)b * H_DIM)
                                     : (out + (size_t)(item - B_DIM) * H_DIM);
                    }
                    s_ptr[tid]  = p;
                    s_item[tid] = item;
                }
                __syncthreads();

                float acc[2][2][3][4];
                #pragma unroll
                for (int mb = 0; mb < 2; mb++)
                    #pragma unroll
                    for (int jb = 0; jb < 2; jb++)
                        #pragma unroll
                        for (int gg = 0; gg < 3; gg++)
                            #pragma unroll
                            for (int q = 0; q < 4; q++) acc[mb][jb][gg][q] = 0.f;

                const float* p = s_ptr[garow];

                // preamble: B via cp.async stage 0, A regs -> split stage 0
                #pragma unroll
                for (int gg = 0; gg < 3; gg++) {
                    const size_t src = (size_t)gbrow * H3 + gg * H_DIM + j0 + gbcb;
                    cp_async16(&Bh[gbrow * LDBw + gg * 64 + gbcb], &g_wh_h[src]);
                    cp_async16(&Bl[gbrow * LDBw + gg * 64 + gbcb], &g_wh_l[src]);
                }
                cp_commit();
                float4 va[2];
                #pragma unroll
                for (int q = 0; q < 2; q++)
                    va[q] = p ? *(const float4*)(p + gacb + q * 4)
                              : make_float4(0.f, 0.f, 0.f, 0.f);
                #pragma unroll
                for (int q = 0; q < 2; q++)
                    split4(&Ah[garow * LDA + gacb + q * 4],
                           &Al[garow * LDA + gacb + q * 4], va[q]);

                int st = 0;
                for (int k0 = 0; k0 < H_DIM; k0 += 32) {
                    cp_wait_all();
                    __syncthreads();
                    const bool more = (k0 + 32 < H_DIM);
                    if (more) {
                        const int ns = st ^ 1;
                        #pragma unroll
                        for (int gg = 0; gg < 3; gg++) {
                            const size_t src = (size_t)(k0 + 32 + gbrow) * H3 + gg * H_DIM + j0 + gbcb;
                            cp_async16(&Bh[ns * WV_B_ST + gbrow * LDBw + gg * 64 + gbcb], &g_wh_h[src]);
                            cp_async16(&Bl[ns * WV_B_ST + gbrow * LDBw + gg * 64 + gbcb], &g_wh_l[src]);
                        }
                        cp_commit();
                        #pragma unroll
                        for (int q = 0; q < 2; q++)
                            va[q] = p ? *(const float4*)(p + k0 + 32 + gacb + q * 4)
                                      : make_float4(0.f, 0.f, 0.f, 0.f);
                    }

                    const __nv_bfloat16* cAh = Ah + st * WV_A_ST;
                    const __nv_bfloat16* cAl = Al + st * WV_A_ST;
                    const __nv_bfloat16* cBh = Bh + st * WV_B_ST;
                    const __nv_bfloat16* cBl = Bl + st * WV_B_ST;
                    #pragma unroll
                    for (int ks = 0; ks < 2; ks++) {
                        const int kk = ks * 16;
                        uint32_t afh[2][4], afl[2][4];
                        #pragma unroll
                        for (int mb = 0; mb < 2; mb++) {
                            const int rr = wm + mb * 16 + (lane & 15);
                            const int cc = kk + (lane >> 4) * 8;
                            ldsm_x4(afh[mb], smem_u32(&cAh[rr * LDA + cc]));
                            ldsm_x4(afl[mb], smem_u32(&cAl[rr * LDA + cc]));
                        }
                        #pragma unroll
                        for (int gg = 0; gg < 3; gg++) {
                            uint32_t bh4[4], bl4[4];
                            const int br2 = kk + (lane & 15);
                            const int bc2 = gg * 64 + wj + (lane >> 4) * 8;
                            ldsm_x4t(bh4, smem_u32(&cBh[br2 * LDBw + bc2]));
                            ldsm_x4t(bl4, smem_u32(&cBl[br2 * LDBw + bc2]));
                            #pragma unroll
                            for (int jb = 0; jb < 2; jb++) {
                                #pragma unroll
                                for (int mb = 0; mb < 2; mb++) {
                                    mma_bf16(acc[mb][jb][gg], afh[mb], &bh4[jb * 2]);
                                    mma_bf16(acc[mb][jb][gg], afh[mb], &bl4[jb * 2]);
                                    mma_bf16(acc[mb][jb][gg], afl[mb], &bh4[jb * 2]);
                                }
                            }
                        }
                    }

                    if (more) {
                        const int ns = st ^ 1;
                        #pragma unroll
                        for (int q = 0; q < 2; q++)
                            split4(&Ah[ns * WV_A_ST + garow * LDA + gacb + q * 4],
                                   &Al[ns * WV_A_ST + garow * LDA + gacb + q * 4], va[q]);
                    }
                    st ^= 1;
                }

                // Fused GRU epilogue (fast transcendentals)
                #pragma unroll
                for (int jb = 0; jb < 2; jb++) {
                    const int j = j0 + wj + jb * 8 + 2 * tg;
                    const float2 bn2 = *(const float2*)&bhn[j];
                    #pragma unroll
                    for (int mb = 0; mb < 2; mb++) {
                        #pragma unroll
                        for (int half = 0; half < 2; half++) {
                            const int lm = wm + mb * 16 + g + half * 8;
                            if (m0 + lm >= n) continue;
                            const int item = s_item[lm];
                            const float* hp_ptr = s_ptr[lm];
                            const float* gip = g_gi + (size_t)item * H3 + j;
                            const float2 gr = *(const float2*)gip;
                            const float2 gz = *(const float2*)(gip + H_DIM);
                            const float2 gn = *(const float2*)(gip + 2 * H_DIM);
                            const float2 hp = *(const float2*)(hp_ptr + j);
                            const float aR0 = acc[mb][jb][0][half * 2 + 0];
                            const float aR1 = acc[mb][jb][0][half * 2 + 1];
                            const float aZ0 = acc[mb][jb][1][half * 2 + 0];
                            const float aZ1 = acc[mb][jb][1][half * 2 + 1];
                            const float aN0 = acc[mb][jb][2][half * 2 + 0];
                            const float aN1 = acc[mb][jb][2][half * 2 + 1];
                            const float r0 = fast_sigmoid(gr.x + aR0);
                            const float r1 = fast_sigmoid(gr.y + aR1);
                            const float z0 = fast_sigmoid(gz.x + aZ0);
                            const float z1 = fast_sigmoid(gz.y + aZ1);
                            const float n0 = fast_tanh(gn.x + r0 * (aN0 + bn2.x));
                            const float n1 = fast_tanh(gn.y + r1 * (aN1 + bn2.y));
                            float2 o;
                            o.x = (1.f - z0) * n0 + z0 * hp.x;
                            o.y = (1.f - z1) * n1 + z1 * hp.y;
                            *(float2*)(out + (size_t)item * H_DIM + j) = o;
                        }
                    }
                }
            }
        } else {
            // ----------------- FINE PATH (16-row tiles, single-stage) -----
            const int ntiles = ((n + 15) >> 4) << 2;
            for (int tile = blockIdx.x; tile < ntiles; tile += gridDim.x) {
                const int m0 = (tile >> 2) << 4;
                const int j0 = (tile & 3) << 6;

                __syncthreads();
                if (tid < 16) {
                    const int m = m0 + tid;
                    const float* p = nullptr;
                    int item = 0;
                    if (m < n) {
                        item = g_items[off + m];
                        const int t = item >> 8;
                        const int b = item & 255;
                        p = (t == 0) ? (carry + (size_t)b * H_DIM)
                                     : (out + (size_t)(item - B_DIM) * H_DIM);
                    }
                    s_ptr[tid]  = p;
                    s_item[tid] = item;
                }
                __syncthreads();

                float accf[3][4];
                #pragma unroll
                for (int gg = 0; gg < 3; gg++)
                    #pragma unroll
                    for (int q = 0; q < 4; q++) accf[gg][q] = 0.f;

                for (int k0 = 0; k0 < H_DIM; k0 += 32) {
                    // B stage 0 via cp.async
                    #pragma unroll
                    for (int gg = 0; gg < 3; gg++) {
                        const size_t src = (size_t)(k0 + gbrow) * H3 + gg * H_DIM + j0 + gbcb;
                        cp_async16(&Bh[gbrow * LDBw + gg * 64 + gbcb], &g_wh_h[src]);
                        cp_async16(&Bl[gbrow * LDBw + gg * 64 + gbcb], &g_wh_l[src]);
                    }
                    cp_commit();
                    // A: 16 rows x 32 cols, threads 0..127 (row = tid>>3, 4 cols)
                    if (tid < 128) {
                        const int rowf = tid >> 3, c4 = (tid & 7) * 4;
                        const float* pf = s_ptr[rowf];
                        float4 v = pf ? *(const float4*)(pf + k0 + c4)
                                      : make_float4(0.f, 0.f, 0.f, 0.f);
                        split4(&Ah[rowf * LDA + c4], &Al[rowf * LDA + c4], v);
                    }
                    cp_wait_all();
                    __syncthreads();

                    #pragma unroll
                    for (int ks = 0; ks < 2; ks++) {
                        const int kk = ks * 16;
                        uint32_t afh[4], afl[4];
                        const int rr = lane & 15;
                        const int cc = kk + (lane >> 4) * 8;
                        ldsm_x4(afh, smem_u32(&Ah[rr * LDA + cc]));
                        ldsm_x4(afl, smem_u32(&Al[rr * LDA + cc]));
                        #pragma unroll
                        for (int gg = 0; gg < 3; gg++) {
                            uint32_t bh2[2], bl2[2];
                            const int br2 = kk + (lane & 15);
                            const int bc2 = gg * 64 + wid * 8;
                            ldsm_x2t(bh2, smem_u32(&Bh[br2 * LDBw + bc2]));
                            ldsm_x2t(bl2, smem_u32(&Bl[br2 * LDBw + bc2]));
                            mma_bf16(accf[gg], afh, bh2);
                            mma_bf16(accf[gg], afh, bl2);
                            mma_bf16(accf[gg], afl, bh2);
                        }
                    }
                    __syncthreads();   // buffers reused next k-iter
                }

                // Fine epilogue: warp covers m16 x (8 cols at j0 + wid*8)
                {
                    const int j = j0 + wid * 8 + 2 * tg;
                    const float2 bn2 = *(const float2*)&bhn[j];
                    #pragma unroll
                    for (int half = 0; half < 2; half++) {
                        const int lm = g + half * 8;
                        if (m0 + lm >= n) continue;
                        const int item = s_item[lm];
                        const float* hp_ptr = s_ptr[lm];
                        const float* gip = g_gi + (size_t)item * H3 + j;
                        const float2 gr = *(const float2*)gip;
                        const float2 gz = *(const float2*)(gip + H_DIM);
                        const float2 gn = *(const float2*)(gip + 2 * H_DIM);
                        const float2 hp = *(const float2*)(hp_ptr + j);
                        const float aR0 = accf[0][half * 2 + 0];
                        const float aR1 = accf[0][half * 2 + 1];
                        const float aZ0 = accf[1][half * 2 + 0];
                        const float aZ1 = accf[1][half * 2 + 1];
                        const float aN0 = accf[2][half * 2 + 0];
                        const float aN1 = accf[2][half * 2 + 1];
                        const float r0 = fast_sigmoid(gr.x + aR0);
                        const float r1 = fast_sigmoid(gr.y + aR1);
                        const float z0 = fast_sigmoid(gz.x + aZ0);
                        const float z1 = fast_sigmoid(gz.y + aZ1);
                        const float n0 = fast_tanh(gn.x + r0 * (aN0 + bn2.x));
                        const float n1 = fast_tanh(gn.y + r1 * (aN1 + bn2.y));
                        float2 o;
                        o.x = (1.f - z0) * n0 + z0 * hp.x;
                        o.y = (1.f - z1) * n1 + z1 * hp.y;
                        *(float2*)(out + (size_t)item * H_DIM + j) = o;
                    }
                }
            }
        }

        off += n;
        grid_barrier(sense);
    }
}

// ---------------------------------------------------------------------------
extern "C" void kernel_launch(void* const* d_in, const int* in_sizes, int n_in,
                              void* d_out, int out_size) {
    const float* ins    = (const float*)d_in[0];   // [T,B,H]
    const int*   resets = (const int*)d_in[1];     // [T,B] int32 (bool promoted)
    const float* carry  = (const float*)d_in[2];   // [B,H]
    const float* Wi     = (const float*)d_in[3];   // [H,3H]
    const float* bi     = (const float*)d_in[4];   // [3H]
    const float* Wh     = (const float*)d_in[5];   // [H,3H]
    const float* bhn    = (const float*)d_in[6];   // [H]
    float*       out    = (float*)d_out;           // [T,B,H]

    static bool attr_done = false;
    if (!attr_done) {
        cudaFuncSetAttribute(gi_gemm, cudaFuncAttributeMaxDynamicSharedMemorySize, GI_SMEM_BYTES);
        cudaFuncSetAttribute(gru_waves, cudaFuncAttributeMaxDynamicSharedMemorySize, WV_SMEM_BYTES);
        attr_done = true;
    }

    // Phase 0: weight split + schedule build + barrier reset (one kernel)
    setup<<<769, 256>>>(Wi, Wh, resets);

    // Phase 1: all input gates via tensor cores
    dim3 g1(H3 / 128, M_TOT / 128);
    gi_gemm<<<g1, 256, GI_SMEM_BYTES>>>(ins, bi);

    // Phase 2: all reset rows — pure pointwise, no GEMM, no dependencies
    flat_reset<<<1184, 256>>>(bhn, out);

    // Phase 3: dependency waves (non-reset rows only) — persistent, 2 CTAs/SM
    gru_waves<<<NCTA2, 256, WV_SMEM_BYTES>>>(carry, bhn, out);
}

// round 15
// speedup vs baseline: 1.4851x; 1.4851x over previous
#include <cuda_runtime.h>
#include <cuda_bf16.h>
#include <cstdint>
#include <math.h>

#define T_DIM 512
#define B_DIM 256
#define H_DIM 256
#define H3    768
#define M_TOT (T_DIM * B_DIM)
#define NCTA2 296   // persistent wave kernel: 2 CTAs per SM
#define FINE_MAX 2368   // waves with n <= this use 16-row fine tiles

// Precomputed input gates gi = ins @ Wi + bi : [T*B][3H] fp32 (402 MB)
__device__ float g_gi[(size_t)M_TOT * H3];
// Pre-split weights (bf16 hi/lo), row-major [K][3H]
__device__ __nv_bfloat16 g_wi_h[H_DIM * H3], g_wi_l[H_DIM * H3];
__device__ __nv_bfloat16 g_wh_h[H_DIM * H3], g_wh_l[H_DIM * H3];
// Scheduling: wave items (non-reset rows) + flat items (reset rows, gh==0)
__device__ int g_wave_cnt[T_DIM];
__device__ int g_items[M_TOT];         // item = (t<<8)|b, grouped by depth
__device__ int g_flat_cnt;
__device__ int g_flat_items[M_TOT];
// Tree grid-barrier state (re-initialized by setup each replay)
__device__ unsigned g_bar_grp[8 * 32];   // group counters, 128B apart
__device__ unsigned g_bar_root;
__device__ volatile unsigned g_bar_sense;

// ---------------------------------------------------------------------------
// PTX helpers
// ---------------------------------------------------------------------------
__device__ __forceinline__ uint32_t smem_u32(const void* p) {
    return (uint32_t)__cvta_generic_to_shared(p);
}
__device__ __forceinline__ void ldsm_x4(uint32_t* r, uint32_t a) {
    asm volatile("ldmatrix.sync.aligned.m8n8.x4.shared.b16 {%0,%1,%2,%3}, [%4];"
                 : "=r"(r[0]), "=r"(r[1]), "=r"(r[2]), "=r"(r[3]) : "r"(a));
}
__device__ __forceinline__ void ldsm_x4t(uint32_t* r, uint32_t a) {
    asm volatile("ldmatrix.sync.aligned.m8n8.x4.trans.shared.b16 {%0,%1,%2,%3}, [%4];"
                 : "=r"(r[0]), "=r"(r[1]), "=r"(r[2]), "=r"(r[3]) : "r"(a));
}
__device__ __forceinline__ void ldsm_x2t(uint32_t* r, uint32_t a) {
    asm volatile("ldmatrix.sync.aligned.m8n8.x2.trans.shared.b16 {%0,%1}, [%2];"
                 : "=r"(r[0]), "=r"(r[1]) : "r"(a));
}
__device__ __forceinline__ void mma_bf16(float* c, const uint32_t* a, const uint32_t* b) {
    asm volatile("mma.sync.aligned.m16n8k16.row.col.f32.bf16.bf16.f32 "
                 "{%0,%1,%2,%3}, {%4,%5,%6,%7}, {%8,%9}, {%0,%1,%2,%3};"
                 : "+f"(c[0]), "+f"(c[1]), "+f"(c[2]), "+f"(c[3])
                 : "r"(a[0]), "r"(a[1]), "r"(a[2]), "r"(a[3]),
                   "r"(b[0]), "r"(b[1]));
}
__device__ __forceinline__ void split4(__nv_bfloat16* dh, __nv_bfloat16* dl, float4 v) {
    float vv[4] = { v.x, v.y, v.z, v.w };
    __nv_bfloat16 h[4], l[4];
    #pragma unroll
    for (int i = 0; i < 4; i++) {
        h[i] = __float2bfloat16(vv[i]);
        l[i] = __float2bfloat16(vv[i] - __bfloat162float(h[i]));
    }
    *(__nv_bfloat162*)&dh[0] = __nv_bfloat162(h[0], h[1]);
    *(__nv_bfloat162*)&dh[2] = __nv_bfloat162(h[2], h[3]);
    *(__nv_bfloat162*)&dl[0] = __nv_bfloat162(l[0], l[1]);
    *(__nv_bfloat162*)&dl[2] = __nv_bfloat162(l[2], l[3]);
}
// cp.async (LDGSTS): 16B global->shared, no register staging
__device__ __forceinline__ void cp_async16(void* smem_dst, const void* gmem_src) {
    asm volatile("cp.async.cg.shared.global [%0], [%1], 16;"
                 :: "r"(smem_u32(smem_dst)), "l"(gmem_src) : "memory");
}
__device__ __forceinline__ void cp_commit() {
    asm volatile("cp.async.commit_group;" ::: "memory");
}
__device__ __forceinline__ void cp_wait_all() {
    asm volatile("cp.async.wait_group 0;" ::: "memory");
}

// ---------------------------------------------------------------------------
// Kernel 0: setup. Blocks 0..767: split Wi/Wh to bf16 hi/lo.
// Block 768: build wave/flat schedule from resets + reset barrier state.
// ---------------------------------------------------------------------------
__global__ __launch_bounds__(256) void setup(const float* __restrict__ Wi,
                                             const float* __restrict__ Wh,
                                             const int* __restrict__ resets) {
    const int tid = threadIdx.x;
    if (blockIdx.x < 768) {
        const int i = blockIdx.x * 256 + tid;
        float v = Wi[i];
        __nv_bfloat16 h = __float2bfloat16(v);
        g_wi_h[i] = h;
        g_wi_l[i] = __float2bfloat16(v - __bfloat162float(h));
        v = Wh[i];
        h = __float2bfloat16(v);
        g_wh_h[i] = h;
        g_wh_l[i] = __float2bfloat16(v - __bfloat162float(h));
        return;
    }
    // schedule-building block
    __shared__ int s_cnt[T_DIM + 1];
    __shared__ int s_cur[T_DIM + 1];
    for (int i = tid; i < T_DIM + 1; i += 256) s_cnt[i] = 0;
    if (tid < 8 * 32) g_bar_grp[tid] = 0;
    if (tid == 0) { g_bar_root = 0; g_bar_sense = 0; }
    __syncthreads();

    const int b = tid;
    {   // Pass 1: counts
        int d = 0;
        bool prev_reset = true;
        for (int t = 0; t < T_DIM; t++) {
            const int rst = resets[t * B_DIM + b];
            int key;
            if (rst) { key = T_DIM; prev_reset = true; }
            else     { d = prev_reset ? 0 : d + 1; key = d; prev_reset = false; }
            const unsigned mask = __match_any_sync(0xffffffffu, key);
            const int leader = __ffs(mask) - 1;
            if ((tid & 31) == leader) atomicAdd(&s_cnt[key], __popc(mask));
        }
    }
    __syncthreads();
    if (tid == 0) {
        int acc = 0;
        for (int i = 0; i < T_DIM; i++) {
            const int c = s_cnt[i];
            g_wave_cnt[i] = c;
            s_cur[i] = acc;
            acc += c;
        }
        g_flat_cnt = s_cnt[T_DIM];
        s_cur[T_DIM] = 0;
    }
    __syncthreads();
    {   // Pass 2: fill lists
        int d = 0;
        bool prev_reset = true;
        for (int t = 0; t < T_DIM; t++) {
            const int rst = resets[t * B_DIM + b];
            int key;
            if (rst) { key = T_DIM; prev_reset = true; }
            else     { d = prev_reset ? 0 : d + 1; key = d; prev_reset = false; }
            const unsigned mask = __match_any_sync(0xffffffffu, key);
            const int leader = __ffs(mask) - 1;
            int base = 0;
            if ((tid & 31) == leader) base = atomicAdd(&s_cur[key], __popc(mask));
            base = __shfl_sync(0xffffffffu, base, leader);
            const int rank = __popc(mask & ((1u << (tid & 31)) - 1u));
            const int item = (t << 8) | b;
            if (key == T_DIM) g_flat_items[base + rank] = item;
            else              g_items[base + rank]      = item;
        }
    }
}

// ---------------------------------------------------------------------------
// Kernel 1: GI = ins @ Wi + bi — mma.sync, double-buffered, cp.async B tiles.
// BM=128, BN=128, BK=32. 8 warps: 4(M) x 2(N); warp tile m32 x n64.
// ---------------------------------------------------------------------------
#define LDA 40
#define LDBg 136
#define GI_A_ST (128 * LDA)
#define GI_B_ST (32 * LDBg)
#define GI_SMEM_BYTES ((2 * GI_A_ST * 2 + 2 * GI_B_ST * 2) * 2)
__global__ __launch_bounds__(256, 2) void gi_gemm(const float* __restrict__ A,
                                                  const float* __restrict__ bi) {
    extern __shared__ __nv_bfloat16 sm[];
    __nv_bfloat16* Ah = sm;
    __nv_bfloat16* Al = Ah + 2 * GI_A_ST;
    __nv_bfloat16* Bh = Al + 2 * GI_A_ST;
    __nv_bfloat16* Bl = Bh + 2 * GI_B_ST;

    const int tid = threadIdx.x;
    const int wid = tid >> 5, lane = tid & 31;
    const int m0 = blockIdx.y * 128, n0 = blockIdx.x * 128;
    const int wm = (wid >> 1) * 32, wn = (wid & 1) * 64;
    const int g = lane >> 2, tg = lane & 3;

    const int arow = tid >> 1, acb = (tid & 1) * 16;
    const int brow = tid >> 3, bcb = (tid & 7) * 16;

    float acc[2][8][4];
    #pragma unroll
    for (int mb = 0; mb < 2; mb++)
        #pragma unroll
        for (int nb = 0; nb < 8; nb++)
            #pragma unroll
            for (int q = 0; q < 4; q++) acc[mb][nb][q] = 0.f;

    float4 pa[4];
    // preamble: B via cp.async into stage 0, A via regs -> split store stage 0
    {
        const size_t src = (size_t)brow * H3 + n0 + bcb;
        cp_async16(&Bh[brow * LDBg + bcb],     &g_wi_h[src]);
        cp_async16(&Bh[brow * LDBg + bcb + 8], &g_wi_h[src + 8]);
        cp_async16(&Bl[brow * LDBg + bcb],     &g_wi_l[src]);
        cp_async16(&Bl[brow * LDBg + bcb + 8], &g_wi_l[src + 8]);
        cp_commit();
    }
    #pragma unroll
    for (int q = 0; q < 4; q++)
        pa[q] = *(const float4*)&A[(size_t)(m0 + arow) * H_DIM + acb + q * 4];
    #pragma unroll
    for (int q = 0; q < 4; q++)
        split4(&Ah[arow * LDA + acb + q * 4], &Al[arow * LDA + acb + q * 4], pa[q]);

    int st = 0;
    for (int k0 = 0; k0 < H_DIM; k0 += 32) {
        cp_wait_all();          // B(st) landed (own-thread) ...
        __syncthreads();        // ... and visible to all; A(st) visible; ns free
        const bool more = (k0 + 32 < H_DIM);
        if (more) {
            const int ns = st ^ 1;
            const size_t src = (size_t)(k0 + 32 + brow) * H3 + n0 + bcb;
            cp_async16(&Bh[ns * GI_B_ST + brow * LDBg + bcb],     &g_wi_h[src]);
            cp_async16(&Bh[ns * GI_B_ST + brow * LDBg + bcb + 8], &g_wi_h[src + 8]);
            cp_async16(&Bl[ns * GI_B_ST + brow * LDBg + bcb],     &g_wi_l[src]);
            cp_async16(&Bl[ns * GI_B_ST + brow * LDBg + bcb + 8], &g_wi_l[src + 8]);
            cp_commit();
            #pragma unroll
            for (int q = 0; q < 4; q++)
                pa[q] = *(const float4*)&A[(size_t)(m0 + arow) * H_DIM + k0 + 32 + acb + q * 4];
        }

        const __nv_bfloat16* cAh = Ah + st * GI_A_ST;
        const __nv_bfloat16* cAl = Al + st * GI_A_ST;
        const __nv_bfloat16* cBh = Bh + st * GI_B_ST;
        const __nv_bfloat16* cBl = Bl + st * GI_B_ST;
        #pragma unroll
        for (int ks = 0; ks < 2; ks++) {
            const int kk = ks * 16;
            uint32_t afh[2][4], afl[2][4];
            #pragma unroll
            for (int mb = 0; mb < 2; mb++) {
                const int r = wm + mb * 16 + (lane & 15);
                const int c = kk + (lane >> 4) * 8;
                ldsm_x4(afh[mb], smem_u32(&cAh[r * LDA + c]));
                ldsm_x4(afl[mb], smem_u32(&cAl[r * LDA + c]));
            }
            #pragma unroll
            for (int nb2 = 0; nb2 < 4; nb2++) {
                uint32_t bh4[4], bl4[4];
                const int br2 = kk + (lane & 15);
                const int bc2 = wn + nb2 * 16 + (lane >> 4) * 8;
                ldsm_x4t(bh4, smem_u32(&cBh[br2 * LDBg + bc2]));
                ldsm_x4t(bl4, smem_u32(&cBl[br2 * LDBg + bc2]));
                #pragma unroll
                for (int hh = 0; hh < 2; hh++) {
                    #pragma unroll
                    for (int mb = 0; mb < 2; mb++) {
                        mma_bf16(acc[mb][nb2 * 2 + hh], afh[mb], &bh4[hh * 2]);
                        mma_bf16(acc[mb][nb2 * 2 + hh], afh[mb], &bl4[hh * 2]);
                        mma_bf16(acc[mb][nb2 * 2 + hh], afl[mb], &bh4[hh * 2]);
                    }
                }
            }
        }

        if (more) {
            const int ns = st ^ 1;
            #pragma unroll
            for (int q = 0; q < 4; q++)
                split4(&Ah[ns * GI_A_ST + arow * LDA + acb + q * 4],
                       &Al[ns * GI_A_ST + arow * LDA + acb + q * 4], pa[q]);
        }
        st ^= 1;
    }

    #pragma unroll
    for (int nb = 0; nb < 8; nb++) {
        const int col = n0 + wn + nb * 8 + 2 * tg;
        const float2 bb = *(const float2*)&bi[col];
        #pragma unroll
        for (int mb = 0; mb < 2; mb++) {
            const int row = m0 + wm + mb * 16 + g;
            float2 o0 = { acc[mb][nb][0] + bb.x, acc[mb][nb][1] + bb.y };
            float2 o1 = { acc[mb][nb][2] + bb.x, acc[mb][nb][3] + bb.y };
            *(float2*)&g_gi[(size_t)row * H3 + col]       = o0;
            *(float2*)&g_gi[(size_t)(row + 8) * H3 + col] = o1;
        }
    }
}

// ---------------------------------------------------------------------------
// Kernel 2b: flat rows (reset -> h_prev==0, gh==0). Pure pointwise, DRAM-bound.
// ---------------------------------------------------------------------------
__global__ __launch_bounds__(256) void flat_reset(const float* __restrict__ bhn,
                                                  float* __restrict__ out) {
    const int nit = g_flat_cnt;
    const int total = nit * 64;
    for (int idx = blockIdx.x * 256 + threadIdx.x; idx < total;
         idx += gridDim.x * 256) {
        const int it = idx >> 6;
        const int j  = (idx & 63) * 4;
        const int item = g_flat_items[it];
        const float* gi = g_gi + (size_t)item * H3 + j;
        const float4 gr = *(const float4*)gi;
        const float4 gz = *(const float4*)(gi + H_DIM);
        const float4 gn = *(const float4*)(gi + 2 * H_DIM);
        const float4 bn = *(const float4*)&bhn[j];
        const float grv[4] = { gr.x, gr.y, gr.z, gr.w };
        const float gzv[4] = { gz.x, gz.y, gz.z, gz.w };
        const float gnv[4] = { gn.x, gn.y, gn.z, gn.w };
        const float bnv[4] = { bn.x, bn.y, bn.z, bn.w };
        float o[4];
        #pragma unroll
        for (int c = 0; c < 4; c++) {
            const float r  = 1.f / (1.f + expf(-grv[c]));
            const float z  = 1.f / (1.f + expf(-gzv[c]));
            const float nn = tanhf(gnv[c] + r * bnv[c]);
            o[c] = (1.f - z) * nn;
        }
        *(float4*)(out + (size_t)item * H_DIM + j) =
            make_float4(o[0], o[1], o[2], o[3]);
    }
}

// ---------------------------------------------------------------------------
// Tree grid barrier: 8 groups (gridDim.x divisible by 8) + root.
// ---------------------------------------------------------------------------
__device__ __forceinline__ void grid_barrier(unsigned& sense) {
    __syncthreads();
    sense ^= 1u;
    if (threadIdx.x == 0) {
        __threadfence();
        const unsigned grp = blockIdx.x & 7;
        const unsigned gsize = gridDim.x >> 3;
        const unsigned pos = atomicAdd(&g_bar_grp[grp * 32], 1u);
        if (pos == gsize - 1) {
            atomicExch(&g_bar_grp[grp * 32], 0u);
            const unsigned rpos = atomicAdd(&g_bar_root, 1u);
            if (rpos == 7) {
                atomicExch(&g_bar_root, 0u);
                __threadfence();
                g_bar_sense = sense;
            }
        }
        while (g_bar_sense != sense) { __nanosleep(32); }
        __threadfence();
    }
    __syncthreads();
}

// ---------------------------------------------------------------------------
// Kernel 3: wave GEMM scan — mma.sync, cp.async, 2 CTAs/SM.
// Coarse path: 64-row tiles, double-buffered (fat waves).
// Fine path:   16-row tiles, single-stage (tail waves, n <= FINE_MAX).
// ---------------------------------------------------------------------------
#define LDBw 200
#define WV_A_ST (64 * LDA)
#define WV_B_ST (32 * LDBw)
#define WV_SMEM_BYTES ((2 * WV_A_ST * 2 + 2 * WV_B_ST * 2) * 2)
__global__ __launch_bounds__(256, 2) void gru_waves(
    const float* __restrict__ carry,    // [B,H]
    const float* __restrict__ bhn,      // [H]
    float*       __restrict__ out)      // [T,B,H]
{
    extern __shared__ __nv_bfloat16 sm[];
    __nv_bfloat16* Ah = sm;
    __nv_bfloat16* Al = Ah + 2 * WV_A_ST;
    __nv_bfloat16* Bh = Al + 2 * WV_A_ST;
    __nv_bfloat16* Bl = Bh + 2 * WV_B_ST;
    __shared__ const float* s_ptr[64];
    __shared__ int s_item[64];

    const int tid = threadIdx.x;
    const int wid = tid >> 5, lane = tid & 31;
    const int wm = (wid >> 2) * 32, wj = (wid & 3) * 16;
    const int g = lane >> 2, tg = lane & 3;

    const int garow = tid >> 2, gacb = (tid & 3) * 8;   // A: 64 x 32
    const int gbrow = tid >> 3, gbcb = (tid & 7) * 8;   // B per gate: 32 x 64

    unsigned sense = 0;
    int off = 0;

    for (int w = 0; w < T_DIM; w++) {
        const int n = g_wave_cnt[w];
        if (n == 0) break;

        if (n > FINE_MAX) {
            // ----------------- COARSE PATH (64-row tiles) -----------------
            const int ntiles = ((n + 63) >> 6) << 2;
            for (int tile = blockIdx.x; tile < ntiles; tile += gridDim.x) {
                const int m0 = (tile >> 2) << 6;
                const int j0 = (tile & 3) << 6;

                __syncthreads();
                if (tid < 64) {
                    const int m = m0 + tid;
                    const float* p = nullptr;
                    int item = 0;
                    if (m < n) {
                        item = g_items[off + m];
                        const int t = item >> 8;
                        const int b = item & 255;
                        p = (t == 0) ? (carry + (size_t)b * H_DIM)
                                     : (out + (size_t)(item - B_DIM) * H_DIM);
                    }
                    s_ptr[tid]  = p;
                    s_item[tid] = item;
                }
                __syncthreads();

                float acc[2][2][3][4];
                #pragma unroll
                for (int mb = 0; mb < 2; mb++)
                    #pragma unroll
                    for (int jb = 0; jb < 2; jb++)
                        #pragma unroll
                        for (int gg = 0; gg < 3; gg++)
                            #pragma unroll
                            for (int q = 0; q < 4; q++) acc[mb][jb][gg][q] = 0.f;

                const float* p = s_ptr[garow];

                // preamble: B via cp.async stage 0, A regs -> split stage 0
                #pragma unroll
                for (int gg = 0; gg < 3; gg++) {
                    const size_t src = (size_t)gbrow * H3 + gg * H_DIM + j0 + gbcb;
                    cp_async16(&Bh[gbrow * LDBw + gg * 64 + gbcb], &g_wh_h[src]);
                    cp_async16(&Bl[gbrow * LDBw + gg * 64 + gbcb], &g_wh_l[src]);
                }
                cp_commit();
                float4 va[2];
                #pragma unroll
                for (int q = 0; q < 2; q++)
                    va[q] = p ? *(const float4*)(p + gacb + q * 4)
                              : make_float4(0.f, 0.f, 0.f, 0.f);
                #pragma unroll
                for (int q = 0; q < 2; q++)
                    split4(&Ah[garow * LDA + gacb + q * 4],
                           &Al[garow * LDA + gacb + q * 4], va[q]);

                int st = 0;
                for (int k0 = 0; k0 < H_DIM; k0 += 32) {
                    cp_wait_all();
                    __syncthreads();
                    const bool more = (k0 + 32 < H_DIM);
                    if (more) {
                        const int ns = st ^ 1;
                        #pragma unroll
                        for (int gg = 0; gg < 3; gg++) {
                            const size_t src = (size_t)(k0 + 32 + gbrow) * H3 + gg * H_DIM + j0 + gbcb;
                            cp_async16(&Bh[ns * WV_B_ST + gbrow * LDBw + gg * 64 + gbcb], &g_wh_h[src]);
                            cp_async16(&Bl[ns * WV_B_ST + gbrow * LDBw + gg * 64 + gbcb], &g_wh_l[src]);
                        }
                        cp_commit();
                        #pragma unroll
                        for (int q = 0; q < 2; q++)
                            va[q] = p ? *(const float4*)(p + k0 + 32 + gacb + q * 4)
                                      : make_float4(0.f, 0.f, 0.f, 0.f);
                    }

                    const __nv_bfloat16* cAh = Ah + st * WV_A_ST;
                    const __nv_bfloat16* cAl = Al + st * WV_A_ST;
                    const __nv_bfloat16* cBh = Bh + st * WV_B_ST;
                    const __nv_bfloat16* cBl = Bl + st * WV_B_ST;
                    #pragma unroll
                    for (int ks = 0; ks < 2; ks++) {
                        const int kk = ks * 16;
                        uint32_t afh[2][4], afl[2][4];
                        #pragma unroll
                        for (int mb = 0; mb < 2; mb++) {
                            const int rr = wm + mb * 16 + (lane & 15);
                            const int cc = kk + (lane >> 4) * 8;
                            ldsm_x4(afh[mb], smem_u32(&cAh[rr * LDA + cc]));
                            ldsm_x4(afl[mb], smem_u32(&cAl[rr * LDA + cc]));
                        }
                        #pragma unroll
                        for (int gg = 0; gg < 3; gg++) {
                            uint32_t bh4[4], bl4[4];
                            const int br2 = kk + (lane & 15);
                            const int bc2 = gg * 64 + wj + (lane >> 4) * 8;
                            ldsm_x4t(bh4, smem_u32(&cBh[br2 * LDBw + bc2]));
                            ldsm_x4t(bl4, smem_u32(&cBl[br2 * LDBw + bc2]));
                            #pragma unroll
                            for (int jb = 0; jb < 2; jb++) {
                                #pragma unroll
                                for (int mb = 0; mb < 2; mb++) {
                                    mma_bf16(acc[mb][jb][gg], afh[mb], &bh4[jb * 2]);
                                    mma_bf16(acc[mb][jb][gg], afh[mb], &bl4[jb * 2]);
                                    mma_bf16(acc[mb][jb][gg], afl[mb], &bh4[jb * 2]);
                                }
                            }
                        }
                    }

                    if (more) {
                        const int ns = st ^ 1;
                        #pragma unroll
                        for (int q = 0; q < 2; q++)
                            split4(&Ah[ns * WV_A_ST + garow * LDA + gacb + q * 4],
                                   &Al[ns * WV_A_ST + garow * LDA + gacb + q * 4], va[q]);
                    }
                    st ^= 1;
                }

                // Fused GRU epilogue
                #pragma unroll
                for (int jb = 0; jb < 2; jb++) {
                    const int j = j0 + wj + jb * 8 + 2 * tg;
                    const float2 bn2 = *(const float2*)&bhn[j];
                    #pragma unroll
                    for (int mb = 0; mb < 2; mb++) {
                        #pragma unroll
                        for (int half = 0; half < 2; half++) {
                            const int lm = wm + mb * 16 + g + half * 8;
                            if (m0 + lm >= n) continue;
                            const int item = s_item[lm];
                            const float* hp_ptr = s_ptr[lm];
                            const float* gip = g_gi + (size_t)item * H3 + j;
                            const float2 gr = *(const float2*)gip;
                            const float2 gz = *(const float2*)(gip + H_DIM);
                            const float2 gn = *(const float2*)(gip + 2 * H_DIM);
                            const float2 hp = *(const float2*)(hp_ptr + j);
                            const float aR0 = acc[mb][jb][0][half * 2 + 0];
                            const float aR1 = acc[mb][jb][0][half * 2 + 1];
                            const float aZ0 = acc[mb][jb][1][half * 2 + 0];
                            const float aZ1 = acc[mb][jb][1][half * 2 + 1];
                            const float aN0 = acc[mb][jb][2][half * 2 + 0];
                            const float aN1 = acc[mb][jb][2][half * 2 + 1];
                            const float r0 = 1.f / (1.f + expf(-(gr.x + aR0)));
                            const float r1 = 1.f / (1.f + expf(-(gr.y + aR1)));
                            const float z0 = 1.f / (1.f + expf(-(gz.x + aZ0)));
                            const float z1 = 1.f / (1.f + expf(-(gz.y + aZ1)));
                            const float n0 = tanhf(gn.x + r0 * (aN0 + bn2.x));
                            const float n1 = tanhf(gn.y + r1 * (aN1 + bn2.y));
                            float2 o;
                            o.x = (1.f - z0) * n0 + z0 * hp.x;
                            o.y = (1.f - z1) * n1 + z1 * hp.y;
                            *(float2*)(out + (size_t)item * H_DIM + j) = o;
                        }
                    }
                }
            }
        } else {
            // ----------------- FINE PATH (16-row tiles, single-stage) -----
            const int ntiles = ((n + 15) >> 4) << 2;
            for (int tile = blockIdx.x; tile < ntiles; tile += gridDim.x) {
                const int m0 = (tile >> 2) << 4;
                const int j0 = (tile & 3) << 6;

                __syncthreads();
                if (tid < 16) {
                    const int m = m0 + tid;
                    const float* p = nullptr;
                    int item = 0;
                    if (m < n) {
                        item = g_items[off + m];
                        const int t = item >> 8;
                        const int b = item & 255;
                        p = (t == 0) ? (carry + (size_t)b * H_DIM)
                                     : (out + (size_t)(item - B_DIM) * H_DIM);
                    }
                    s_ptr[tid]  = p;
                    s_item[tid] = item;
                }
                __syncthreads();

                float accf[3][4];
                #pragma unroll
                for (int gg = 0; gg < 3; gg++)
                    #pragma unroll
                    for (int q = 0; q < 4; q++) accf[gg][q] = 0.f;

                for (int k0 = 0; k0 < H_DIM; k0 += 32) {
                    // B stage 0 via cp.async
                    #pragma unroll
                    for (int gg = 0; gg < 3; gg++) {
                        const size_t src = (size_t)(k0 + gbrow) * H3 + gg * H_DIM + j0 + gbcb;
                        cp_async16(&Bh[gbrow * LDBw + gg * 64 + gbcb], &g_wh_h[src]);
                        cp_async16(&Bl[gbrow * LDBw + gg * 64 + gbcb], &g_wh_l[src]);
                    }
                    cp_commit();
                    // A: 16 rows x 32 cols, threads 0..127 (row = tid>>3, 4 cols)
                    if (tid < 128) {
                        const int rowf = tid >> 3, c4 = (tid & 7) * 4;
                        const float* pf = s_ptr[rowf];
                        float4 v = pf ? *(const float4*)(pf + k0 + c4)
                                      : make_float4(0.f, 0.f, 0.f, 0.f);
                        split4(&Ah[rowf * LDA + c4], &Al[rowf * LDA + c4], v);
                    }
                    cp_wait_all();
                    __syncthreads();

                    #pragma unroll
                    for (int ks = 0; ks < 2; ks++) {
                        const int kk = ks * 16;
                        uint32_t afh[4], afl[4];
                        const int rr = lane & 15;
                        const int cc = kk + (lane >> 4) * 8;
                        ldsm_x4(afh, smem_u32(&Ah[rr * LDA + cc]));
                        ldsm_x4(afl, smem_u32(&Al[rr * LDA + cc]));
                        #pragma unroll
                        for (int gg = 0; gg < 3; gg++) {
                            uint32_t bh2[2], bl2[2];
                            const int br2 = kk + (lane & 15);
                            const int bc2 = gg * 64 + wid * 8;
                            ldsm_x2t(bh2, smem_u32(&Bh[br2 * LDBw + bc2]));
                            ldsm_x2t(bl2, smem_u32(&Bl[br2 * LDBw + bc2]));
                            mma_bf16(accf[gg], afh, bh2);
                            mma_bf16(accf[gg], afh, bl2);
                            mma_bf16(accf[gg], afl, bh2);
                        }
                    }
                    __syncthreads();   // buffers reused next k-iter
                }

                // Fine epilogue: warp covers m16 x (8 cols at j0 + wid*8)
                {
                    const int j = j0 + wid * 8 + 2 * tg;
                    const float2 bn2 = *(const float2*)&bhn[j];
                    #pragma unroll
                    for (int half = 0; half < 2; half++) {
                        const int lm = g + half * 8;
                        if (m0 + lm >= n) continue;
                        const int item = s_item[lm];
                        const float* hp_ptr = s_ptr[lm];
                        const float* gip = g_gi + (size_t)item * H3 + j;
                        const float2 gr = *(const float2*)gip;
                        const float2 gz = *(const float2*)(gip + H_DIM);
                        const float2 gn = *(const float2*)(gip + 2 * H_DIM);
                        const float2 hp = *(const float2*)(hp_ptr + j);
                        const float aR0 = accf[0][half * 2 + 0];
                        const float aR1 = accf[0][half * 2 + 1];
                        const float aZ0 = accf[1][half * 2 + 0];
                        const float aZ1 = accf[1][half * 2 + 1];
                        const float aN0 = accf[2][half * 2 + 0];
                        const float aN1 = accf[2][half * 2 + 1];
                        const float r0 = 1.f / (1.f + expf(-(gr.x + aR0)));
                        const float r1 = 1.f / (1.f + expf(-(gr.y + aR1)));
                        const float z0 = 1.f / (1.f + expf(-(gz.x + aZ0)));
                        const float z1 = 1.f / (1.f + expf(-(gz.y + aZ1)));
                        const float n0 = tanhf(gn.x + r0 * (aN0 + bn2.x));
                        const float n1 = tanhf(gn.y + r1 * (aN1 + bn2.y));
                        float2 o;
                        o.x = (1.f - z0) * n0 + z0 * hp.x;
                        o.y = (1.f - z1) * n1 + z1 * hp.y;
                        *(float2*)(out + (size_t)item * H_DIM + j) = o;
                    }
                }
            }
        }

        off += n;
        grid_barrier(sense);
    }
}

// ---------------------------------------------------------------------------
extern "C" void kernel_launch(void* const* d_in, const int* in_sizes, int n_in,
                              void* d_out, int out_size) {
    const float* ins    = (const float*)d_in[0];   // [T,B,H]
    const int*   resets = (const int*)d_in[1];     // [T,B] int32 (bool promoted)
    const float* carry  = (const float*)d_in[2];   // [B,H]
    const float* Wi     = (const float*)d_in[3];   // [H,3H]
    const float* bi     = (const float*)d_in[4];   // [3H]
    const float* Wh     = (const float*)d_in[5];   // [H,3H]
    const float* bhn    = (const float*)d_in[6];   // [H]
    float*       out    = (float*)d_out;           // [T,B,H]

    static bool attr_done = false;
    if (!attr_done) {
        cudaFuncSetAttribute(gi_gemm, cudaFuncAttributeMaxDynamicSharedMemorySize, GI_SMEM_BYTES);
        cudaFuncSetAttribute(gru_waves, cudaFuncAttributeMaxDynamicSharedMemorySize, WV_SMEM_BYTES);
        attr_done = true;
    }

    // Phase 0: weight split + schedule build + barrier reset (one kernel)
    setup<<<769, 256>>>(Wi, Wh, resets);

    // Phase 1: all input gates via tensor cores
    dim3 g1(H3 / 128, M_TOT / 128);
    gi_gemm<<<g1, 256, GI_SMEM_BYTES>>>(ins, bi);

    // Phase 2: all reset rows — pure pointwise, no GEMM, no dependencies
    flat_reset<<<1184, 256>>>(bhn, out);

    // Phase 3: dependency waves (non-reset rows only) — persistent, 2 CTAs/SM
    gru_waves<<<NCTA2, 256, WV_SMEM_BYTES>>>(carry, bhn, out);
}

// round 16
// speedup vs baseline: 1.6928x; 1.1399x over previous
#include <cuda_runtime.h>
#include <cuda_fp16.h>
#include <cstdint>
#include <math.h>

#define T_DIM 512
#define B_DIM 256
#define H_DIM 256
#define H3    768
#define M_TOT (T_DIM * B_DIM)
#define NCTA2 296   // persistent wave kernel: 2 CTAs per SM
#define FINE_MAX 2368   // waves with n <= this use 16-row fine tiles

// Precomputed input gates gi = ins @ Wi + bi : [T*B][3H] fp32 (402 MB)
__device__ float g_gi[(size_t)M_TOT * H3];
// Pre-split weights (fp16 hi/lo pair = near-exact), row-major [K][3H]
__device__ __half g_wi_h[H_DIM * H3], g_wi_l[H_DIM * H3];
__device__ __half g_wh_h[H_DIM * H3], g_wh_l[H_DIM * H3];
// Scheduling: wave items (non-reset rows) + flat items (reset rows, gh==0)
__device__ int g_wave_cnt[T_DIM];
__device__ int g_items[M_TOT];         // item = (t<<8)|b, grouped by depth
__device__ int g_flat_cnt;
__device__ int g_flat_items[M_TOT];
// Tree grid-barrier state (re-initialized by setup each replay)
__device__ unsigned g_bar_grp[8 * 32];   // group counters, 128B apart
__device__ unsigned g_bar_root;
__device__ volatile unsigned g_bar_sense;

// ---------------------------------------------------------------------------
// PTX helpers
// ---------------------------------------------------------------------------
__device__ __forceinline__ uint32_t smem_u32(const void* p) {
    return (uint32_t)__cvta_generic_to_shared(p);
}
__device__ __forceinline__ void ldsm_x4(uint32_t* r, uint32_t a) {
    asm volatile("ldmatrix.sync.aligned.m8n8.x4.shared.b16 {%0,%1,%2,%3}, [%4];"
                 : "=r"(r[0]), "=r"(r[1]), "=r"(r[2]), "=r"(r[3]) : "r"(a));
}
__device__ __forceinline__ void ldsm_x4t(uint32_t* r, uint32_t a) {
    asm volatile("ldmatrix.sync.aligned.m8n8.x4.trans.shared.b16 {%0,%1,%2,%3}, [%4];"
                 : "=r"(r[0]), "=r"(r[1]), "=r"(r[2]), "=r"(r[3]) : "r"(a));
}
__device__ __forceinline__ void ldsm_x2t(uint32_t* r, uint32_t a) {
    asm volatile("ldmatrix.sync.aligned.m8n8.x2.trans.shared.b16 {%0,%1}, [%2];"
                 : "=r"(r[0]), "=r"(r[1]) : "r"(a));
}
// fp16 inputs, fp32 accumulate
__device__ __forceinline__ void mma_f16(float* c, const uint32_t* a, const uint32_t* b) {
    asm volatile("mma.sync.aligned.m16n8k16.row.col.f32.f16.f16.f32 "
                 "{%0,%1,%2,%3}, {%4,%5,%6,%7}, {%8,%9}, {%0,%1,%2,%3};"
                 : "+f"(c[0]), "+f"(c[1]), "+f"(c[2]), "+f"(c[3])
                 : "r"(a[0]), "r"(a[1]), "r"(a[2]), "r"(a[3]),
                   "r"(b[0]), "r"(b[1]));
}
// fp32x4 -> fp16x4 (single quantization; data-side 2^-12 rel error)
__device__ __forceinline__ void cvt4(__half* d, float4 v) {
    *(__half2*)&d[0] = __floats2half2_rn(v.x, v.y);
    *(__half2*)&d[2] = __floats2half2_rn(v.z, v.w);
}
// cp.async (LDGSTS): 16B global->shared, no register staging
__device__ __forceinline__ void cp_async16(void* smem_dst, const void* gmem_src) {
    asm volatile("cp.async.cg.shared.global [%0], [%1], 16;"
                 :: "r"(smem_u32(smem_dst)), "l"(gmem_src) : "memory");
}
__device__ __forceinline__ void cp_commit() {
    asm volatile("cp.async.commit_group;" ::: "memory");
}
__device__ __forceinline__ void cp_wait_all() {
    asm volatile("cp.async.wait_group 0;" ::: "memory");
}

// ---------------------------------------------------------------------------
// Kernel 0: setup. Blocks 0..767: split Wi/Wh to fp16 hi/lo.
// Block 768: build wave/flat schedule from resets + reset barrier state.
// ---------------------------------------------------------------------------
__global__ __launch_bounds__(256) void setup(const float* __restrict__ Wi,
                                             const float* __restrict__ Wh,
                                             const int* __restrict__ resets) {
    const int tid = threadIdx.x;
    if (blockIdx.x < 768) {
        const int i = blockIdx.x * 256 + tid;
        float v = Wi[i];
        __half h = __float2half(v);
        g_wi_h[i] = h;
        g_wi_l[i] = __float2half(v - __half2float(h));
        v = Wh[i];
        h = __float2half(v);
        g_wh_h[i] = h;
        g_wh_l[i] = __float2half(v - __half2float(h));
        return;
    }
    // schedule-building block
    __shared__ int s_cnt[T_DIM + 1];
    __shared__ int s_cur[T_DIM + 1];
    for (int i = tid; i < T_DIM + 1; i += 256) s_cnt[i] = 0;
    if (tid < 8 * 32) g_bar_grp[tid] = 0;
    if (tid == 0) { g_bar_root = 0; g_bar_sense = 0; }
    __syncthreads();

    const int b = tid;
    {   // Pass 1: counts
        int d = 0;
        bool prev_reset = true;
        for (int t = 0; t < T_DIM; t++) {
            const int rst = resets[t * B_DIM + b];
            int key;
            if (rst) { key = T_DIM; prev_reset = true; }
            else     { d = prev_reset ? 0 : d + 1; key = d; prev_reset = false; }
            const unsigned mask = __match_any_sync(0xffffffffu, key);
            const int leader = __ffs(mask) - 1;
            if ((tid & 31) == leader) atomicAdd(&s_cnt[key], __popc(mask));
        }
    }
    __syncthreads();
    if (tid == 0) {
        int acc = 0;
        for (int i = 0; i < T_DIM; i++) {
            const int c = s_cnt[i];
            g_wave_cnt[i] = c;
            s_cur[i] = acc;
            acc += c;
        }
        g_flat_cnt = s_cnt[T_DIM];
        s_cur[T_DIM] = 0;
    }
    __syncthreads();
    {   // Pass 2: fill lists
        int d = 0;
        bool prev_reset = true;
        for (int t = 0; t < T_DIM; t++) {
            const int rst = resets[t * B_DIM + b];
            int key;
            if (rst) { key = T_DIM; prev_reset = true; }
            else     { d = prev_reset ? 0 : d + 1; key = d; prev_reset = false; }
            const unsigned mask = __match_any_sync(0xffffffffu, key);
            const int leader = __ffs(mask) - 1;
            int base = 0;
            if ((tid & 31) == leader) base = atomicAdd(&s_cur[key], __popc(mask));
            base = __shfl_sync(0xffffffffu, base, leader);
            const int rank = __popc(mask & ((1u << (tid & 31)) - 1u));
            const int item = (t << 8) | b;
            if (key == T_DIM) g_flat_items[base + rank] = item;
            else              g_items[base + rank]      = item;
        }
    }
}

// ---------------------------------------------------------------------------
// Kernel 1: GI = ins @ Wi + bi — 2-term fp16 mma, double-buffered, cp.async B.
// BM=128, BN=128, BK=32. 8 warps: 4(M) x 2(N); warp tile m32 x n64.
// ---------------------------------------------------------------------------
#define LDA 40
#define LDBg 136
#define GI_A_ST (128 * LDA)
#define GI_B_ST (32 * LDBg)
#define GI_SMEM_BYTES ((2 * GI_A_ST + 4 * GI_B_ST) * 2)
__global__ __launch_bounds__(256, 2) void gi_gemm(const float* __restrict__ A,
                                                  const float* __restrict__ bi) {
    extern __shared__ __half sm[];
    __half* Ah = sm;                       // single A rep (fp16)
    __half* Bh = Ah + 2 * GI_A_ST;
    __half* Bl = Bh + 2 * GI_B_ST;

    const int tid = threadIdx.x;
    const int wid = tid >> 5, lane = tid & 31;
    const int m0 = blockIdx.y * 128, n0 = blockIdx.x * 128;
    const int wm = (wid >> 1) * 32, wn = (wid & 1) * 64;
    const int g = lane >> 2, tg = lane & 3;

    const int arow = tid >> 1, acb = (tid & 1) * 16;
    const int brow = tid >> 3, bcb = (tid & 7) * 16;

    float acc[2][8][4];
    #pragma unroll
    for (int mb = 0; mb < 2; mb++)
        #pragma unroll
        for (int nb = 0; nb < 8; nb++)
            #pragma unroll
            for (int q = 0; q < 4; q++) acc[mb][nb][q] = 0.f;

    float4 pa[4];
    // preamble: B via cp.async into stage 0, A via regs -> fp16 store stage 0
    {
        const size_t src = (size_t)brow * H3 + n0 + bcb;
        cp_async16(&Bh[brow * LDBg + bcb],     &g_wi_h[src]);
        cp_async16(&Bh[brow * LDBg + bcb + 8], &g_wi_h[src + 8]);
        cp_async16(&Bl[brow * LDBg + bcb],     &g_wi_l[src]);
        cp_async16(&Bl[brow * LDBg + bcb + 8], &g_wi_l[src + 8]);
        cp_commit();
    }
    #pragma unroll
    for (int q = 0; q < 4; q++)
        pa[q] = *(const float4*)&A[(size_t)(m0 + arow) * H_DIM + acb + q * 4];
    #pragma unroll
    for (int q = 0; q < 4; q++)
        cvt4(&Ah[arow * LDA + acb + q * 4], pa[q]);

    int st = 0;
    for (int k0 = 0; k0 < H_DIM; k0 += 32) {
        cp_wait_all();          // B(st) landed (own-thread) ...
        __syncthreads();        // ... and visible to all; A(st) visible; ns free
        const bool more = (k0 + 32 < H_DIM);
        if (more) {
            const int ns = st ^ 1;
            const size_t src = (size_t)(k0 + 32 + brow) * H3 + n0 + bcb;
            cp_async16(&Bh[ns * GI_B_ST + brow * LDBg + bcb],     &g_wi_h[src]);
            cp_async16(&Bh[ns * GI_B_ST + brow * LDBg + bcb + 8], &g_wi_h[src + 8]);
            cp_async16(&Bl[ns * GI_B_ST + brow * LDBg + bcb],     &g_wi_l[src]);
            cp_async16(&Bl[ns * GI_B_ST + brow * LDBg + bcb + 8], &g_wi_l[src + 8]);
            cp_commit();
            #pragma unroll
            for (int q = 0; q < 4; q++)
                pa[q] = *(const float4*)&A[(size_t)(m0 + arow) * H_DIM + k0 + 32 + acb + q * 4];
        }

        const __half* cAh = Ah + st * GI_A_ST;
        const __half* cBh = Bh + st * GI_B_ST;
        const __half* cBl = Bl + st * GI_B_ST;
        #pragma unroll
        for (int ks = 0; ks < 2; ks++) {
            const int kk = ks * 16;
            uint32_t afh[2][4];
            #pragma unroll
            for (int mb = 0; mb < 2; mb++) {
                const int r = wm + mb * 16 + (lane & 15);
                const int c = kk + (lane >> 4) * 8;
                ldsm_x4(afh[mb], smem_u32(&cAh[r * LDA + c]));
            }
            #pragma unroll
            for (int nb2 = 0; nb2 < 4; nb2++) {
                uint32_t bh4[4], bl4[4];
                const int br2 = kk + (lane & 15);
                const int bc2 = wn + nb2 * 16 + (lane >> 4) * 8;
                ldsm_x4t(bh4, smem_u32(&cBh[br2 * LDBg + bc2]));
                ldsm_x4t(bl4, smem_u32(&cBl[br2 * LDBg + bc2]));
                #pragma unroll
                for (int hh = 0; hh < 2; hh++) {
                    #pragma unroll
                    for (int mb = 0; mb < 2; mb++) {
                        mma_f16(acc[mb][nb2 * 2 + hh], afh[mb], &bh4[hh * 2]);
                        mma_f16(acc[mb][nb2 * 2 + hh], afh[mb], &bl4[hh * 2]);
                    }
                }
            }
        }

        if (more) {
            const int ns = st ^ 1;
            #pragma unroll
            for (int q = 0; q < 4; q++)
                cvt4(&Ah[ns * GI_A_ST + arow * LDA + acb + q * 4], pa[q]);
        }
        st ^= 1;
    }

    #pragma unroll
    for (int nb = 0; nb < 8; nb++) {
        const int col = n0 + wn + nb * 8 + 2 * tg;
        const float2 bb = *(const float2*)&bi[col];
        #pragma unroll
        for (int mb = 0; mb < 2; mb++) {
            const int row = m0 + wm + mb * 16 + g;
            float2 o0 = { acc[mb][nb][0] + bb.x, acc[mb][nb][1] + bb.y };
            float2 o1 = { acc[mb][nb][2] + bb.x, acc[mb][nb][3] + bb.y };
            *(float2*)&g_gi[(size_t)row * H3 + col]       = o0;
            *(float2*)&g_gi[(size_t)(row + 8) * H3 + col] = o1;
        }
    }
}

// ---------------------------------------------------------------------------
// Kernel 2b: flat rows (reset -> h_prev==0, gh==0). Pure pointwise, DRAM-bound.
// ---------------------------------------------------------------------------
__global__ __launch_bounds__(256) void flat_reset(const float* __restrict__ bhn,
                                                  float* __restrict__ out) {
    const int nit = g_flat_cnt;
    const int total = nit * 64;
    for (int idx = blockIdx.x * 256 + threadIdx.x; idx < total;
         idx += gridDim.x * 256) {
        const int it = idx >> 6;
        const int j  = (idx & 63) * 4;
        const int item = g_flat_items[it];
        const float* gi = g_gi + (size_t)item * H3 + j;
        const float4 gr = *(const float4*)gi;
        const float4 gz = *(const float4*)(gi + H_DIM);
        const float4 gn = *(const float4*)(gi + 2 * H_DIM);
        const float4 bn = *(const float4*)&bhn[j];
        const float grv[4] = { gr.x, gr.y, gr.z, gr.w };
        const float gzv[4] = { gz.x, gz.y, gz.z, gz.w };
        const float gnv[4] = { gn.x, gn.y, gn.z, gn.w };
        const float bnv[4] = { bn.x, bn.y, bn.z, bn.w };
        float o[4];
        #pragma unroll
        for (int c = 0; c < 4; c++) {
            const float r  = 1.f / (1.f + expf(-grv[c]));
            const float z  = 1.f / (1.f + expf(-gzv[c]));
            const float nn = tanhf(gnv[c] + r * bnv[c]);
            o[c] = (1.f - z) * nn;
        }
        *(float4*)(out + (size_t)item * H_DIM + j) =
            make_float4(o[0], o[1], o[2], o[3]);
    }
}

// ---------------------------------------------------------------------------
// Tree grid barrier: 8 groups (gridDim.x divisible by 8) + root.
// ---------------------------------------------------------------------------
__device__ __forceinline__ void grid_barrier(unsigned& sense) {
    __syncthreads();
    sense ^= 1u;
    if (threadIdx.x == 0) {
        __threadfence();
        const unsigned grp = blockIdx.x & 7;
        const unsigned gsize = gridDim.x >> 3;
        const unsigned pos = atomicAdd(&g_bar_grp[grp * 32], 1u);
        if (pos == gsize - 1) {
            atomicExch(&g_bar_grp[grp * 32], 0u);
            const unsigned rpos = atomicAdd(&g_bar_root, 1u);
            if (rpos == 7) {
                atomicExch(&g_bar_root, 0u);
                __threadfence();
                g_bar_sense = sense;
            }
        }
        while (g_bar_sense != sense) { __nanosleep(32); }
        __threadfence();
    }
    __syncthreads();
}

// ---------------------------------------------------------------------------
// Kernel 3: wave GEMM scan — 2-term fp16 mma, cp.async, 2 CTAs/SM.
// Coarse path: 64-row tiles, double-buffered (fat waves).
// Fine path:   16-row tiles, single-stage (tail waves, n <= FINE_MAX).
// ---------------------------------------------------------------------------
#define LDBw 200
#define WV_A_ST (64 * LDA)
#define WV_B_ST (32 * LDBw)
#define WV_SMEM_BYTES ((2 * WV_A_ST + 4 * WV_B_ST) * 2)
__global__ __launch_bounds__(256, 2) void gru_waves(
    const float* __restrict__ carry,    // [B,H]
    const float* __restrict__ bhn,      // [H]
    float*       __restrict__ out)      // [T,B,H]
{
    extern __shared__ __half sm[];
    __half* Ah = sm;
    __half* Bh = Ah + 2 * WV_A_ST;
    __half* Bl = Bh + 2 * WV_B_ST;
    __shared__ const float* s_ptr[64];
    __shared__ int s_item[64];

    const int tid = threadIdx.x;
    const int wid = tid >> 5, lane = tid & 31;
    const int wm = (wid >> 2) * 32, wj = (wid & 3) * 16;
    const int g = lane >> 2, tg = lane & 3;

    const int garow = tid >> 2, gacb = (tid & 3) * 8;   // A: 64 x 32
    const int gbrow = tid >> 3, gbcb = (tid & 7) * 8;   // B per gate: 32 x 64

    unsigned sense = 0;
    int off = 0;

    for (int w = 0; w < T_DIM; w++) {
        const int n = g_wave_cnt[w];
        if (n == 0) break;

        if (n > FINE_MAX) {
            // ----------------- COARSE PATH (64-row tiles) -----------------
            const int ntiles = ((n + 63) >> 6) << 2;
            for (int tile = blockIdx.x; tile < ntiles; tile += gridDim.x) {
                const int m0 = (tile >> 2) << 6;
                const int j0 = (tile & 3) << 6;

                __syncthreads();
                if (tid < 64) {
                    const int m = m0 + tid;
                    const float* p = nullptr;
                    int item = 0;
                    if (m < n) {
                        item = g_items[off + m];
                        const int t = item >> 8;
                        const int b = item & 255;
                        p = (t == 0) ? (carry + (size_t)b * H_DIM)
                                     : (out + (size_t)(item - B_DIM) * H_DIM);
                    }
                    s_ptr[tid]  = p;
                    s_item[tid] = item;
                }
                __syncthreads();

                float acc[2][2][3][4];
                #pragma unroll
                for (int mb = 0; mb < 2; mb++)
                    #pragma unroll
                    for (int jb = 0; jb < 2; jb++)
                        #pragma unroll
                        for (int gg = 0; gg < 3; gg++)
                            #pragma unroll
                            for (int q = 0; q < 4; q++) acc[mb][jb][gg][q] = 0.f;

                const float* p = s_ptr[garow];

                // preamble: B via cp.async stage 0, A regs -> fp16 stage 0
                #pragma unroll
                for (int gg = 0; gg < 3; gg++) {
                    const size_t src = (size_t)gbrow * H3 + gg * H_DIM + j0 + gbcb;
                    cp_async16(&Bh[gbrow * LDBw + gg * 64 + gbcb], &g_wh_h[src]);
                    cp_async16(&Bl[gbrow * LDBw + gg * 64 + gbcb], &g_wh_l[src]);
                }
                cp_commit();
                float4 va[2];
                #pragma unroll
                for (int q = 0; q < 2; q++)
                    va[q] = p ? *(const float4*)(p + gacb + q * 4)
                              : make_float4(0.f, 0.f, 0.f, 0.f);
                #pragma unroll
                for (int q = 0; q < 2; q++)
                    cvt4(&Ah[garow * LDA + gacb + q * 4], va[q]);

                int st = 0;
                for (int k0 = 0; k0 < H_DIM; k0 += 32) {
                    cp_wait_all();
                    __syncthreads();
                    const bool more = (k0 + 32 < H_DIM);
                    if (more) {
                        const int ns = st ^ 1;
                        #pragma unroll
                        for (int gg = 0; gg < 3; gg++) {
                            const size_t src = (size_t)(k0 + 32 + gbrow) * H3 + gg * H_DIM + j0 + gbcb;
                            cp_async16(&Bh[ns * WV_B_ST + gbrow * LDBw + gg * 64 + gbcb], &g_wh_h[src]);
                            cp_async16(&Bl[ns * WV_B_ST + gbrow * LDBw + gg * 64 + gbcb], &g_wh_l[src]);
                        }
                        cp_commit();
                        #pragma unroll
                        for (int q = 0; q < 2; q++)
                            va[q] = p ? *(const float4*)(p + k0 + 32 + gacb + q * 4)
                                      : make_float4(0.f, 0.f, 0.f, 0.f);
                    }

                    const __half* cAh = Ah + st * WV_A_ST;
                    const __half* cBh = Bh + st * WV_B_ST;
                    const __half* cBl = Bl + st * WV_B_ST;
                    #pragma unroll
                    for (int ks = 0; ks < 2; ks++) {
                        const int kk = ks * 16;
                        uint32_t afh[2][4];
                        #pragma unroll
                        for (int mb = 0; mb < 2; mb++) {
                            const int rr = wm + mb * 16 + (lane & 15);
                            const int cc = kk + (lane >> 4) * 8;
                            ldsm_x4(afh[mb], smem_u32(&cAh[rr * LDA + cc]));
                        }
                        #pragma unroll
                        for (int gg = 0; gg < 3; gg++) {
                            uint32_t bh4[4], bl4[4];
                            const int br2 = kk + (lane & 15);
                            const int bc2 = gg * 64 + wj + (lane >> 4) * 8;
                            ldsm_x4t(bh4, smem_u32(&cBh[br2 * LDBw + bc2]));
                            ldsm_x4t(bl4, smem_u32(&cBl[br2 * LDBw + bc2]));
                            #pragma unroll
                            for (int jb = 0; jb < 2; jb++) {
                                #pragma unroll
                                for (int mb = 0; mb < 2; mb++) {
                                    mma_f16(acc[mb][jb][gg], afh[mb], &bh4[jb * 2]);
                                    mma_f16(acc[mb][jb][gg], afh[mb], &bl4[jb * 2]);
                                }
                            }
                        }
                    }

                    if (more) {
                        const int ns = st ^ 1;
                        #pragma unroll
                        for (int q = 0; q < 2; q++)
                            cvt4(&Ah[ns * WV_A_ST + garow * LDA + gacb + q * 4], va[q]);
                    }
                    st ^= 1;
                }

                // Fused GRU epilogue
                #pragma unroll
                for (int jb = 0; jb < 2; jb++) {
                    const int j = j0 + wj + jb * 8 + 2 * tg;
                    const float2 bn2 = *(const float2*)&bhn[j];
                    #pragma unroll
                    for (int mb = 0; mb < 2; mb++) {
                        #pragma unroll
                        for (int half = 0; half < 2; half++) {
                            const int lm = wm + mb * 16 + g + half * 8;
                            if (m0 + lm >= n) continue;
                            const int item = s_item[lm];
                            const float* hp_ptr = s_ptr[lm];
                            const float* gip = g_gi + (size_t)item * H3 + j;
                            const float2 gr = *(const float2*)gip;
                            const float2 gz = *(const float2*)(gip + H_DIM);
                            const float2 gn = *(const float2*)(gip + 2 * H_DIM);
                            const float2 hp = *(const float2*)(hp_ptr + j);
                            const float aR0 = acc[mb][jb][0][half * 2 + 0];
                            const float aR1 = acc[mb][jb][0][half * 2 + 1];
                            const float aZ0 = acc[mb][jb][1][half * 2 + 0];
                            const float aZ1 = acc[mb][jb][1][half * 2 + 1];
                            const float aN0 = acc[mb][jb][2][half * 2 + 0];
                            const float aN1 = acc[mb][jb][2][half * 2 + 1];
                            const float r0 = 1.f / (1.f + expf(-(gr.x + aR0)));
                            const float r1 = 1.f / (1.f + expf(-(gr.y + aR1)));
                            const float z0 = 1.f / (1.f + expf(-(gz.x + aZ0)));
                            const float z1 = 1.f / (1.f + expf(-(gz.y + aZ1)));
                            const float n0 = tanhf(gn.x + r0 * (aN0 + bn2.x));
                            const float n1 = tanhf(gn.y + r1 * (aN1 + bn2.y));
                            float2 o;
                            o.x = (1.f - z0) * n0 + z0 * hp.x;
                            o.y = (1.f - z1) * n1 + z1 * hp.y;
                            *(float2*)(out + (size_t)item * H_DIM + j) = o;
                        }
                    }
                }
            }
        } else {
            // ----------------- FINE PATH (16-row tiles, single-stage) -----
            const int ntiles = ((n + 15) >> 4) << 2;
            for (int tile = blockIdx.x; tile < ntiles; tile += gridDim.x) {
                const int m0 = (tile >> 2) << 4;
                const int j0 = (tile & 3) << 6;

                __syncthreads();
                if (tid < 16) {
                    const int m = m0 + tid;
                    const float* p = nullptr;
                    int item = 0;
                    if (m < n) {
                        item = g_items[off + m];
                        const int t = item >> 8;
                        const int b = item & 255;
                        p = (t == 0) ? (carry + (size_t)b * H_DIM)
                                     : (out + (size_t)(item - B_DIM) * H_DIM);
                    }
                    s_ptr[tid]  = p;
                    s_item[tid] = item;
                }
                __syncthreads();

                float accf[3][4];
                #pragma unroll
                for (int gg = 0; gg < 3; gg++)
                    #pragma unroll
                    for (int q = 0; q < 4; q++) accf[gg][q] = 0.f;

                for (int k0 = 0; k0 < H_DIM; k0 += 32) {
                    // B stage 0 via cp.async
                    #pragma unroll
                    for (int gg = 0; gg < 3; gg++) {
                        const size_t src = (size_t)(k0 + gbrow) * H3 + gg * H_DIM + j0 + gbcb;
                        cp_async16(&Bh[gbrow * LDBw + gg * 64 + gbcb], &g_wh_h[src]);
                        cp_async16(&Bl[gbrow * LDBw + gg * 64 + gbcb], &g_wh_l[src]);
                    }
                    cp_commit();
                    // A: 16 rows x 32 cols, threads 0..127 (row = tid>>3, 4 cols)
                    if (tid < 128) {
                        const int rowf = tid >> 3, c4 = (tid & 7) * 4;
                        const float* pf = s_ptr[rowf];
                        float4 v = pf ? *(const float4*)(pf + k0 + c4)
                                      : make_float4(0.f, 0.f, 0.f, 0.f);
                        cvt4(&Ah[rowf * LDA + c4], v);
                    }
                    cp_wait_all();
                    __syncthreads();

                    #pragma unroll
                    for (int ks = 0; ks < 2; ks++) {
                        const int kk = ks * 16;
                        uint32_t afh[4];
                        const int rr = lane & 15;
                        const int cc = kk + (lane >> 4) * 8;
                        ldsm_x4(afh, smem_u32(&Ah[rr * LDA + cc]));
                        #pragma unroll
                        for (int gg = 0; gg < 3; gg++) {
                            uint32_t bh2[2], bl2[2];
                            const int br2 = kk + (lane & 15);
                            const int bc2 = gg * 64 + wid * 8;
                            ldsm_x2t(bh2, smem_u32(&Bh[br2 * LDBw + bc2]));
                            ldsm_x2t(bl2, smem_u32(&Bl[br2 * LDBw + bc2]));
                            mma_f16(accf[gg], afh, bh2);
                            mma_f16(accf[gg], afh, bl2);
                        }
                    }
                    __syncthreads();   // buffers reused next k-iter
                }

                // Fine epilogue: warp covers m16 x (8 cols at j0 + wid*8)
                {
                    const int j = j0 + wid * 8 + 2 * tg;
                    const float2 bn2 = *(const float2*)&bhn[j];
                    #pragma unroll
                    for (int half = 0; half < 2; half++) {
                        const int lm = g + half * 8;
                        if (m0 + lm >= n) continue;
                        const int item = s_item[lm];
                        const float* hp_ptr = s_ptr[lm];
                        const float* gip = g_gi + (size_t)item * H3 + j;
                        const float2 gr = *(const float2*)gip;
                        const float2 gz = *(const float2*)(gip + H_DIM);
                        const float2 gn = *(const float2*)(gip + 2 * H_DIM);
                        const float2 hp = *(const float2*)(hp_ptr + j);
                        const float aR0 = accf[0][half * 2 + 0];
                        const float aR1 = accf[0][half * 2 + 1];
                        const float aZ0 = accf[1][half * 2 + 0];
                        const float aZ1 = accf[1][half * 2 + 1];
                        const float aN0 = accf[2][half * 2 + 0];
                        const float aN1 = accf[2][half * 2 + 1];
                        const float r0 = 1.f / (1.f + expf(-(gr.x + aR0)));
                        const float r1 = 1.f / (1.f + expf(-(gr.y + aR1)));
                        const float z0 = 1.f / (1.f + expf(-(gz.x + aZ0)));
                        const float z1 = 1.f / (1.f + expf(-(gz.y + aZ1)));
                        const float n0 = tanhf(gn.x + r0 * (aN0 + bn2.x));
                        const float n1 = tanhf(gn.y + r1 * (aN1 + bn2.y));
                        float2 o;
                        o.x = (1.f - z0) * n0 + z0 * hp.x;
                        o.y = (1.f - z1) * n1 + z1 * hp.y;
                        *(float2*)(out + (size_t)item * H_DIM + j) = o;
                    }
                }
            }
        }

        off += n;
        grid_barrier(sense);
    }
}

// ---------------------------------------------------------------------------
extern "C" void kernel_launch(void* const* d_in, const int* in_sizes, int n_in,
                              void* d_out, int out_size) {
    const float* ins    = (const float*)d_in[0];   // [T,B,H]
    const int*   resets = (const int*)d_in[1];     // [T,B] int32 (bool promoted)
    const float* carry  = (const float*)d_in[2];   // [B,H]
    const float* Wi     = (const float*)d_in[3];   // [H,3H]
    const float* bi     = (const float*)d_in[4];   // [3H]
    const float* Wh     = (const float*)d_in[5];   // [H,3H]
    const float* bhn    = (const float*)d_in[6];   // [H]
    float*       out    = (float*)d_out;           // [T,B,H]

    static bool attr_done = false;
    if (!attr_done) {
        cudaFuncSetAttribute(gi_gemm, cudaFuncAttributeMaxDynamicSharedMemorySize, GI_SMEM_BYTES);
        cudaFuncSetAttribute(gru_waves, cudaFuncAttributeMaxDynamicSharedMemorySize, WV_SMEM_BYTES);
        attr_done = true;
    }

    // Phase 0: weight split + schedule build + barrier reset (one kernel)
    setup<<<769, 256>>>(Wi, Wh, resets);

    // Phase 1: all input gates via tensor cores (2-term fp16)
    dim3 g1(H3 / 128, M_TOT / 128);
    gi_gemm<<<g1, 256, GI_SMEM_BYTES>>>(ins, bi);

    // Phase 2: all reset rows — pure pointwise, no GEMM, no dependencies
    flat_reset<<<1184, 256>>>(bhn, out);

    // Phase 3: dependency waves (non-reset rows only) — persistent, 2 CTAs/SM
    gru_waves<<<NCTA2, 256, WV_SMEM_BYTES>>>(carry, bhn, out);
}

// round 17
// speedup vs baseline: 1.8564x; 1.0966x over previous
#include <cuda_runtime.h>
#include <cuda_fp16.h>
#include <cstdint>
#include <math.h>

#define T_DIM 512
#define B_DIM 256
#define H_DIM 256
#define H3    768
#define M_TOT (T_DIM * B_DIM)
#define NCTA2 296   // persistent wave kernel: 2 CTAs per SM
#define FINE_MAX 2368   // waves with n <= this use 16-row fine tiles

// Precomputed input gates gi = ins @ Wi + bi : [T*B][3H] fp32 (402 MB)
__device__ float g_gi[(size_t)M_TOT * H3];
// Weights: Wi single fp16 (gi path, error-budgeted); Wh fp16 hi/lo (recurrent)
__device__ __half g_wi_h[H_DIM * H3];
__device__ __half g_wh_h[H_DIM * H3], g_wh_l[H_DIM * H3];
// Scheduling: wave items (non-reset rows) + flat items (reset rows, gh==0)
__device__ int g_wave_cnt[T_DIM];
__device__ int g_items[M_TOT];         // item = (t<<8)|b, grouped by depth
__device__ int g_flat_cnt;
__device__ int g_flat_items[M_TOT];
// Tree grid-barrier state (re-initialized by the schedule block each replay)
__device__ unsigned g_bar_grp[8 * 32];   // group counters, 128B apart
__device__ unsigned g_bar_root;
__device__ volatile unsigned g_bar_sense;

// ---------------------------------------------------------------------------
// PTX helpers
// ---------------------------------------------------------------------------
__device__ __forceinline__ uint32_t smem_u32(const void* p) {
    return (uint32_t)__cvta_generic_to_shared(p);
}
__device__ __forceinline__ void ldsm_x4(uint32_t* r, uint32_t a) {
    asm volatile("ldmatrix.sync.aligned.m8n8.x4.shared.b16 {%0,%1,%2,%3}, [%4];"
                 : "=r"(r[0]), "=r"(r[1]), "=r"(r[2]), "=r"(r[3]) : "r"(a));
}
__device__ __forceinline__ void ldsm_x4t(uint32_t* r, uint32_t a) {
    asm volatile("ldmatrix.sync.aligned.m8n8.x4.trans.shared.b16 {%0,%1,%2,%3}, [%4];"
                 : "=r"(r[0]), "=r"(r[1]), "=r"(r[2]), "=r"(r[3]) : "r"(a));
}
__device__ __forceinline__ void ldsm_x2t(uint32_t* r, uint32_t a) {
    asm volatile("ldmatrix.sync.aligned.m8n8.x2.trans.shared.b16 {%0,%1}, [%2];"
                 : "=r"(r[0]), "=r"(r[1]) : "r"(a));
}
// fp16 inputs, fp32 accumulate
__device__ __forceinline__ void mma_f16(float* c, const uint32_t* a, const uint32_t* b) {
    asm volatile("mma.sync.aligned.m16n8k16.row.col.f32.f16.f16.f32 "
                 "{%0,%1,%2,%3}, {%4,%5,%6,%7}, {%8,%9}, {%0,%1,%2,%3};"
                 : "+f"(c[0]), "+f"(c[1]), "+f"(c[2]), "+f"(c[3])
                 : "r"(a[0]), "r"(a[1]), "r"(a[2]), "r"(a[3]),
                   "r"(b[0]), "r"(b[1]));
}
// fp32x4 -> fp16x4
__device__ __forceinline__ void cvt4(__half* d, float4 v) {
    *(__half2*)&d[0] = __floats2half2_rn(v.x, v.y);
    *(__half2*)&d[2] = __floats2half2_rn(v.z, v.w);
}
// cp.async (LDGSTS): 16B global->shared
__device__ __forceinline__ void cp_async16(void* smem_dst, const void* gmem_src) {
    asm volatile("cp.async.cg.shared.global [%0], [%1], 16;"
                 :: "r"(smem_u32(smem_dst)), "l"(gmem_src) : "memory");
}
__device__ __forceinline__ void cp_commit() {
    asm volatile("cp.async.commit_group;" ::: "memory");
}
__device__ __forceinline__ void cp_wait_all() {
    asm volatile("cp.async.wait_group 0;" ::: "memory");
}

// ---------------------------------------------------------------------------
// Kernel 0: weight convert. Wi -> single fp16; Wh -> fp16 hi/lo.
// ---------------------------------------------------------------------------
__global__ __launch_bounds__(256) void w_split(const float* __restrict__ Wi,
                                               const float* __restrict__ Wh) {
    const int i = blockIdx.x * 256 + threadIdx.x;
    if (i < H_DIM * H3) {
        g_wi_h[i] = __float2half(Wi[i]);
        const float v = Wh[i];
        const __half h = __float2half(v);
        g_wh_h[i] = h;
        g_wh_l[i] = __float2half(v - __half2float(h));
    }
}

// ---------------------------------------------------------------------------
// Kernel 1: GI = ins @ Wi + bi — single-term fp16 mma, double-buffered,
// cp.async B. BM=128, BN=128, BK=32. 8 warps: 4(M) x 2(N).
// Grid (6, 1025): row 1024 / x==0 runs the wave/flat schedule build
// concurrently with the GEMM (its outputs are consumed only post-gi).
// ---------------------------------------------------------------------------
#define LDA 40
#define LDBg 136
#define GI_A_ST (128 * LDA)
#define GI_B_ST (32 * LDBg)
#define GI_SMEM_BYTES ((2 * GI_A_ST + 2 * GI_B_ST) * 2)
__global__ __launch_bounds__(256, 2) void gi_gemm(const float* __restrict__ A,
                                                  const float* __restrict__ bi,
                                                  const int* __restrict__ resets) {
    extern __shared__ __half sm[];
    const int tid = threadIdx.x;

    if (blockIdx.y == 1024) {
        // ------- schedule-build block (x==0 only; others exit) -------
        if (blockIdx.x != 0) return;
        int* s_cnt = (int*)sm;
        int* s_cur = s_cnt + T_DIM + 1;
        for (int i = tid; i < T_DIM + 1; i += 256) s_cnt[i] = 0;
        if (tid < 8 * 32) g_bar_grp[tid] = 0;
        if (tid == 0) { g_bar_root = 0; g_bar_sense = 0; }
        __syncthreads();

        const int b = tid;
        {   // Pass 1: counts
            int d = 0;
            bool prev_reset = true;
            for (int t = 0; t < T_DIM; t++) {
                const int rst = resets[t * B_DIM + b];
                int key;
                if (rst) { key = T_DIM; prev_reset = true; }
                else     { d = prev_reset ? 0 : d + 1; key = d; prev_reset = false; }
                const unsigned mask = __match_any_sync(0xffffffffu, key);
                const int leader = __ffs(mask) - 1;
                if ((tid & 31) == leader) atomicAdd(&s_cnt[key], __popc(mask));
            }
        }
        __syncthreads();
        if (tid == 0) {
            int acc = 0;
            for (int i = 0; i < T_DIM; i++) {
                const int c = s_cnt[i];
                g_wave_cnt[i] = c;
                s_cur[i] = acc;
                acc += c;
            }
            g_flat_cnt = s_cnt[T_DIM];
            s_cur[T_DIM] = 0;
        }
        __syncthreads();
        {   // Pass 2: fill lists
            int d = 0;
            bool prev_reset = true;
            for (int t = 0; t < T_DIM; t++) {
                const int rst = resets[t * B_DIM + b];
                int key;
                if (rst) { key = T_DIM; prev_reset = true; }
                else     { d = prev_reset ? 0 : d + 1; key = d; prev_reset = false; }
                const unsigned mask = __match_any_sync(0xffffffffu, key);
                const int leader = __ffs(mask) - 1;
                int base = 0;
                if ((tid & 31) == leader) base = atomicAdd(&s_cur[key], __popc(mask));
                base = __shfl_sync(0xffffffffu, base, leader);
                const int rank = __popc(mask & ((1u << (tid & 31)) - 1u));
                const int item = (t << 8) | b;
                if (key == T_DIM) g_flat_items[base + rank] = item;
                else              g_items[base + rank]      = item;
            }
        }
        return;
    }

    // ------------------------- GEMM blocks -------------------------
    __half* Ah = sm;
    __half* Bh = Ah + 2 * GI_A_ST;

    const int wid = tid >> 5, lane = tid & 31;
    const int m0 = blockIdx.y * 128, n0 = blockIdx.x * 128;
    const int wm = (wid >> 1) * 32, wn = (wid & 1) * 64;
    const int g = lane >> 2, tg = lane & 3;

    const int arow = tid >> 1, acb = (tid & 1) * 16;
    const int brow = tid >> 3, bcb = (tid & 7) * 16;

    float acc[2][8][4];
    #pragma unroll
    for (int mb = 0; mb < 2; mb++)
        #pragma unroll
        for (int nb = 0; nb < 8; nb++)
            #pragma unroll
            for (int q = 0; q < 4; q++) acc[mb][nb][q] = 0.f;

    float4 pa[4];
    // preamble: B via cp.async into stage 0, A via regs -> fp16 store stage 0
    {
        const size_t src = (size_t)brow * H3 + n0 + bcb;
        cp_async16(&Bh[brow * LDBg + bcb],     &g_wi_h[src]);
        cp_async16(&Bh[brow * LDBg + bcb + 8], &g_wi_h[src + 8]);
        cp_commit();
    }
    #pragma unroll
    for (int q = 0; q < 4; q++)
        pa[q] = *(const float4*)&A[(size_t)(m0 + arow) * H_DIM + acb + q * 4];
    #pragma unroll
    for (int q = 0; q < 4; q++)
        cvt4(&Ah[arow * LDA + acb + q * 4], pa[q]);

    int st = 0;
    for (int k0 = 0; k0 < H_DIM; k0 += 32) {
        cp_wait_all();
        __syncthreads();
        const bool more = (k0 + 32 < H_DIM);
        if (more) {
            const int ns = st ^ 1;
            const size_t src = (size_t)(k0 + 32 + brow) * H3 + n0 + bcb;
            cp_async16(&Bh[ns * GI_B_ST + brow * LDBg + bcb],     &g_wi_h[src]);
            cp_async16(&Bh[ns * GI_B_ST + brow * LDBg + bcb + 8], &g_wi_h[src + 8]);
            cp_commit();
            #pragma unroll
            for (int q = 0; q < 4; q++)
                pa[q] = *(const float4*)&A[(size_t)(m0 + arow) * H_DIM + k0 + 32 + acb + q * 4];
        }

        const __half* cAh = Ah + st * GI_A_ST;
        const __half* cBh = Bh + st * GI_B_ST;
        #pragma unroll
        for (int ks = 0; ks < 2; ks++) {
            const int kk = ks * 16;
            uint32_t afh[2][4];
            #pragma unroll
            for (int mb = 0; mb < 2; mb++) {
                const int r = wm + mb * 16 + (lane & 15);
                const int c = kk + (lane >> 4) * 8;
                ldsm_x4(afh[mb], smem_u32(&cAh[r * LDA + c]));
            }
            #pragma unroll
            for (int nb2 = 0; nb2 < 4; nb2++) {
                uint32_t bh4[4];
                const int br2 = kk + (lane & 15);
                const int bc2 = wn + nb2 * 16 + (lane >> 4) * 8;
                ldsm_x4t(bh4, smem_u32(&cBh[br2 * LDBg + bc2]));
                #pragma unroll
                for (int hh = 0; hh < 2; hh++) {
                    #pragma unroll
                    for (int mb = 0; mb < 2; mb++)
                        mma_f16(acc[mb][nb2 * 2 + hh], afh[mb], &bh4[hh * 2]);
                }
            }
        }

        if (more) {
            const int ns = st ^ 1;
            #pragma unroll
            for (int q = 0; q < 4; q++)
                cvt4(&Ah[ns * GI_A_ST + arow * LDA + acb + q * 4], pa[q]);
        }
        st ^= 1;
    }

    #pragma unroll
    for (int nb = 0; nb < 8; nb++) {
        const int col = n0 + wn + nb * 8 + 2 * tg;
        const float2 bb = *(const float2*)&bi[col];
        #pragma unroll
        for (int mb = 0; mb < 2; mb++) {
            const int row = m0 + wm + mb * 16 + g;
            float2 o0 = { acc[mb][nb][0] + bb.x, acc[mb][nb][1] + bb.y };
            float2 o1 = { acc[mb][nb][2] + bb.x, acc[mb][nb][3] + bb.y };
            *(float2*)&g_gi[(size_t)row * H3 + col]       = o0;
            *(float2*)&g_gi[(size_t)(row + 8) * H3 + col] = o1;
        }
    }
}

// ---------------------------------------------------------------------------
// Kernel 2b: flat rows (reset -> h_prev==0, gh==0). Pure pointwise, DRAM-bound.
// ---------------------------------------------------------------------------
__global__ __launch_bounds__(256) void flat_reset(const float* __restrict__ bhn,
                                                  float* __restrict__ out) {
    const int nit = g_flat_cnt;
    const int total = nit * 64;
    for (int idx = blockIdx.x * 256 + threadIdx.x; idx < total;
         idx += gridDim.x * 256) {
        const int it = idx >> 6;
        const int j  = (idx & 63) * 4;
        const int item = g_flat_items[it];
        const float* gi = g_gi + (size_t)item * H3 + j;
        const float4 gr = *(const float4*)gi;
        const float4 gz = *(const float4*)(gi + H_DIM);
        const float4 gn = *(const float4*)(gi + 2 * H_DIM);
        const float4 bn = *(const float4*)&bhn[j];
        const float grv[4] = { gr.x, gr.y, gr.z, gr.w };
        const float gzv[4] = { gz.x, gz.y, gz.z, gz.w };
        const float gnv[4] = { gn.x, gn.y, gn.z, gn.w };
        const float bnv[4] = { bn.x, bn.y, bn.z, bn.w };
        float o[4];
        #pragma unroll
        for (int c = 0; c < 4; c++) {
            const float r  = 1.f / (1.f + expf(-grv[c]));
            const float z  = 1.f / (1.f + expf(-gzv[c]));
            const float nn = tanhf(gnv[c] + r * bnv[c]);
            o[c] = (1.f - z) * nn;
        }
        *(float4*)(out + (size_t)item * H_DIM + j) =
            make_float4(o[0], o[1], o[2], o[3]);
    }
}

// ---------------------------------------------------------------------------
// Tree grid barrier: 8 groups (gridDim.x divisible by 8) + root.
// ---------------------------------------------------------------------------
__device__ __forceinline__ void grid_barrier(unsigned& sense) {
    __syncthreads();
    sense ^= 1u;
    if (threadIdx.x == 0) {
        __threadfence();
        const unsigned grp = blockIdx.x & 7;
        const unsigned gsize = gridDim.x >> 3;
        const unsigned pos = atomicAdd(&g_bar_grp[grp * 32], 1u);
        if (pos == gsize - 1) {
            atomicExch(&g_bar_grp[grp * 32], 0u);
            const unsigned rpos = atomicAdd(&g_bar_root, 1u);
            if (rpos == 7) {
                atomicExch(&g_bar_root, 0u);
                __threadfence();
                g_bar_sense = sense;
            }
        }
        while (g_bar_sense != sense) { __nanosleep(32); }
        __threadfence();
    }
    __syncthreads();
}

// ---------------------------------------------------------------------------
// Kernel 3: wave GEMM scan — 2-term fp16 mma (Wh hi+lo), cp.async, 2 CTAs/SM.
// Coarse path: 64-row tiles, double-buffered. Fine path: 16-row tiles.
// ---------------------------------------------------------------------------
#define LDBw 200
#define WV_A_ST (64 * LDA)
#define WV_B_ST (32 * LDBw)
#define WV_SMEM_BYTES ((2 * WV_A_ST + 4 * WV_B_ST) * 2)
__global__ __launch_bounds__(256, 2) void gru_waves(
    const float* __restrict__ carry,    // [B,H]
    const float* __restrict__ bhn,      // [H]
    float*       __restrict__ out)      // [T,B,H]
{
    extern __shared__ __half sm[];
    __half* Ah = sm;
    __half* Bh = Ah + 2 * WV_A_ST;
    __half* Bl = Bh + 2 * WV_B_ST;
    __shared__ const float* s_ptr[64];
    __shared__ int s_item[64];

    const int tid = threadIdx.x;
    const int wid = tid >> 5, lane = tid & 31;
    const int wm = (wid >> 2) * 32, wj = (wid & 3) * 16;
    const int g = lane >> 2, tg = lane & 3;

    const int garow = tid >> 2, gacb = (tid & 3) * 8;   // A: 64 x 32
    const int gbrow = tid >> 3, gbcb = (tid & 7) * 8;   // B per gate: 32 x 64

    unsigned sense = 0;
    int off = 0;

    for (int w = 0; w < T_DIM; w++) {
        const int n = g_wave_cnt[w];
        if (n == 0) break;

        if (n > FINE_MAX) {
            // ----------------- COARSE PATH (64-row tiles) -----------------
            const int ntiles = ((n + 63) >> 6) << 2;
            for (int tile = blockIdx.x; tile < ntiles; tile += gridDim.x) {
                const int m0 = (tile >> 2) << 6;
                const int j0 = (tile & 3) << 6;

                __syncthreads();
                if (tid < 64) {
                    const int m = m0 + tid;
                    const float* p = nullptr;
                    int item = 0;
                    if (m < n) {
                        item = g_items[off + m];
                        const int t = item >> 8;
                        const int b = item & 255;
                        p = (t == 0) ? (carry + (size_t)b * H_DIM)
                                     : (out + (size_t)(item - B_DIM) * H_DIM);
                    }
                    s_ptr[tid]  = p;
                    s_item[tid] = item;
                }
                __syncthreads();

                float acc[2][2][3][4];
                #pragma unroll
                for (int mb = 0; mb < 2; mb++)
                    #pragma unroll
                    for (int jb = 0; jb < 2; jb++)
                        #pragma unroll
                        for (int gg = 0; gg < 3; gg++)
                            #pragma unroll
                            for (int q = 0; q < 4; q++) acc[mb][jb][gg][q] = 0.f;

                const float* p = s_ptr[garow];

                #pragma unroll
                for (int gg = 0; gg < 3; gg++) {
                    const size_t src = (size_t)gbrow * H3 + gg * H_DIM + j0 + gbcb;
                    cp_async16(&Bh[gbrow * LDBw + gg * 64 + gbcb], &g_wh_h[src]);
                    cp_async16(&Bl[gbrow * LDBw + gg * 64 + gbcb], &g_wh_l[src]);
                }
                cp_commit();
                float4 va[2];
                #pragma unroll
                for (int q = 0; q < 2; q++)
                    va[q] = p ? *(const float4*)(p + gacb + q * 4)
                              : make_float4(0.f, 0.f, 0.f, 0.f);
                #pragma unroll
                for (int q = 0; q < 2; q++)
                    cvt4(&Ah[garow * LDA + gacb + q * 4], va[q]);

                int st = 0;
                for (int k0 = 0; k0 < H_DIM; k0 += 32) {
                    cp_wait_all();
                    __syncthreads();
                    const bool more = (k0 + 32 < H_DIM);
                    if (more) {
                        const int ns = st ^ 1;
                        #pragma unroll
                        for (int gg = 0; gg < 3; gg++) {
                            const size_t src = (size_t)(k0 + 32 + gbrow) * H3 + gg * H_DIM + j0 + gbcb;
                            cp_async16(&Bh[ns * WV_B_ST + gbrow * LDBw + gg * 64 + gbcb], &g_wh_h[src]);
                            cp_async16(&Bl[ns * WV_B_ST + gbrow * LDBw + gg * 64 + gbcb], &g_wh_l[src]);
                        }
                        cp_commit();
                        #pragma unroll
                        for (int q = 0; q < 2; q++)
                            va[q] = p ? *(const float4*)(p + k0 + 32 + gacb + q * 4)
                                      : make_float4(0.f, 0.f, 0.f, 0.f);
                    }

                    const __half* cAh = Ah + st * WV_A_ST;
                    const __half* cBh = Bh + st * WV_B_ST;
                    const __half* cBl = Bl + st * WV_B_ST;
                    #pragma unroll
                    for (int ks = 0; ks < 2; ks++) {
                        const int kk = ks * 16;
                        uint32_t afh[2][4];
                        #pragma unroll
                        for (int mb = 0; mb < 2; mb++) {
                            const int rr = wm + mb * 16 + (lane & 15);
                            const int cc = kk + (lane >> 4) * 8;
                            ldsm_x4(afh[mb], smem_u32(&cAh[rr * LDA + cc]));
                        }
                        #pragma unroll
                        for (int gg = 0; gg < 3; gg++) {
                            uint32_t bh4[4], bl4[4];
                            const int br2 = kk + (lane & 15);
                            const int bc2 = gg * 64 + wj + (lane >> 4) * 8;
                            ldsm_x4t(bh4, smem_u32(&cBh[br2 * LDBw + bc2]));
                            ldsm_x4t(bl4, smem_u32(&cBl[br2 * LDBw + bc2]));
                            #pragma unroll
                            for (int jb = 0; jb < 2; jb++) {
                                #pragma unroll
                                for (int mb = 0; mb < 2; mb++) {
                                    mma_f16(acc[mb][jb][gg], afh[mb], &bh4[jb * 2]);
                                    mma_f16(acc[mb][jb][gg], afh[mb], &bl4[jb * 2]);
                                }
                            }
                        }
                    }

                    if (more) {
                        const int ns = st ^ 1;
                        #pragma unroll
                        for (int q = 0; q < 2; q++)
                            cvt4(&Ah[ns * WV_A_ST + garow * LDA + gacb + q * 4], va[q]);
                    }
                    st ^= 1;
                }

                // Fused GRU epilogue
                #pragma unroll
                for (int jb = 0; jb < 2; jb++) {
                    const int j = j0 + wj + jb * 8 + 2 * tg;
                    const float2 bn2 = *(const float2*)&bhn[j];
                    #pragma unroll
                    for (int mb = 0; mb < 2; mb++) {
                        #pragma unroll
                        for (int half = 0; half < 2; half++) {
                            const int lm = wm + mb * 16 + g + half * 8;
                            if (m0 + lm >= n) continue;
                            const int item = s_item[lm];
                            const float* hp_ptr = s_ptr[lm];
                            const float* gip = g_gi + (size_t)item * H3 + j;
                            const float2 gr = *(const float2*)gip;
                            const float2 gz = *(const float2*)(gip + H_DIM);
                            const float2 gn = *(const float2*)(gip + 2 * H_DIM);
                            const float2 hp = *(const float2*)(hp_ptr + j);
                            const float aR0 = acc[mb][jb][0][half * 2 + 0];
                            const float aR1 = acc[mb][jb][0][half * 2 + 1];
                            const float aZ0 = acc[mb][jb][1][half * 2 + 0];
                            const float aZ1 = acc[mb][jb][1][half * 2 + 1];
                            const float aN0 = acc[mb][jb][2][half * 2 + 0];
                            const float aN1 = acc[mb][jb][2][half * 2 + 1];
                            const float r0 = 1.f / (1.f + expf(-(gr.x + aR0)));
                            const float r1 = 1.f / (1.f + expf(-(gr.y + aR1)));
                            const float z0 = 1.f / (1.f + expf(-(gz.x + aZ0)));
                            const float z1 = 1.f / (1.f + expf(-(gz.y + aZ1)));
                            const float n0 = tanhf(gn.x + r0 * (aN0 + bn2.x));
                            const float n1 = tanhf(gn.y + r1 * (aN1 + bn2.y));
                            float2 o;
                            o.x = (1.f - z0) * n0 + z0 * hp.x;
                            o.y = (1.f - z1) * n1 + z1 * hp.y;
                            *(float2*)(out + (size_t)item * H_DIM + j) = o;
                        }
                    }
                }
            }
        } else {
            // ----------------- FINE PATH (16-row tiles, single-stage) -----
            const int ntiles = ((n + 15) >> 4) << 2;
            for (int tile = blockIdx.x; tile < ntiles; tile += gridDim.x) {
                const int m0 = (tile >> 2) << 4;
                const int j0 = (tile & 3) << 6;

                __syncthreads();
                if (tid < 16) {
                    const int m = m0 + tid;
                    const float* p = nullptr;
                    int item = 0;
                    if (m < n) {
                        item = g_items[off + m];
                        const int t = item >> 8;
                        const int b = item & 255;
                        p = (t == 0) ? (carry + (size_t)b * H_DIM)
                                     : (out + (size_t)(item - B_DIM) * H_DIM);
                    }
                    s_ptr[tid]  = p;
                    s_item[tid] = item;
                }
                __syncthreads();

                float accf[3][4];
                #pragma unroll
                for (int gg = 0; gg < 3; gg++)
                    #pragma unroll
                    for (int q = 0; q < 4; q++) accf[gg][q] = 0.f;

                for (int k0 = 0; k0 < H_DIM; k0 += 32) {
                    #pragma unroll
                    for (int gg = 0; gg < 3; gg++) {
                        const size_t src = (size_t)(k0 + gbrow) * H3 + gg * H_DIM + j0 + gbcb;
                        cp_async16(&Bh[gbrow * LDBw + gg * 64 + gbcb], &g_wh_h[src]);
                        cp_async16(&Bl[gbrow * LDBw + gg * 64 + gbcb], &g_wh_l[src]);
                    }
                    cp_commit();
                    if (tid < 128) {
                        const int rowf = tid >> 3, c4 = (tid & 7) * 4;
                        const float* pf = s_ptr[rowf];
                        float4 v = pf ? *(const float4*)(pf + k0 + c4)
                                      : make_float4(0.f, 0.f, 0.f, 0.f);
                        cvt4(&Ah[rowf * LDA + c4], v);
                    }
                    cp_wait_all();
                    __syncthreads();

                    #pragma unroll
                    for (int ks = 0; ks < 2; ks++) {
                        const int kk = ks * 16;
                        uint32_t afh[4];
                        const int rr = lane & 15;
                        const int cc = kk + (lane >> 4) * 8;
                        ldsm_x4(afh, smem_u32(&Ah[rr * LDA + cc]));
                        #pragma unroll
                        for (int gg = 0; gg < 3; gg++) {
                            uint32_t bh2[2], bl2[2];
                            const int br2 = kk + (lane & 15);
                            const int bc2 = gg * 64 + wid * 8;
                            ldsm_x2t(bh2, smem_u32(&Bh[br2 * LDBw + bc2]));
                            ldsm_x2t(bl2, smem_u32(&Bl[br2 * LDBw + bc2]));
                            mma_f16(accf[gg], afh, bh2);
                            mma_f16(accf[gg], afh, bl2);
                        }
                    }
                    __syncthreads();   // buffers reused next k-iter
                }

                // Fine epilogue: warp covers m16 x (8 cols at j0 + wid*8)
                {
                    const int j = j0 + wid * 8 + 2 * tg;
                    const float2 bn2 = *(const float2*)&bhn[j];
                    #pragma unroll
                    for (int half = 0; half < 2; half++) {
                        const int lm = g + half * 8;
                        if (m0 + lm >= n) continue;
                        const int item = s_item[lm];
                        const float* hp_ptr = s_ptr[lm];
                        const float* gip = g_gi + (size_t)item * H3 + j;
                        const float2 gr = *(const float2*)gip;
                        const float2 gz = *(const float2*)(gip + H_DIM);
                        const float2 gn = *(const float2*)(gip + 2 * H_DIM);
                        const float2 hp = *(const float2*)(hp_ptr + j);
                        const float aR0 = accf[0][half * 2 + 0];
                        const float aR1 = accf[0][half * 2 + 1];
                        const float aZ0 = accf[1][half * 2 + 0];
                        const float aZ1 = accf[1][half * 2 + 1];
                        const float aN0 = accf[2][half * 2 + 0];
                        const float aN1 = accf[2][half * 2 + 1];
                        const float r0 = 1.f / (1.f + expf(-(gr.x + aR0)));
                        const float r1 = 1.f / (1.f + expf(-(gr.y + aR1)));
                        const float z0 = 1.f / (1.f + expf(-(gz.x + aZ0)));
                        const float z1 = 1.f / (1.f + expf(-(gz.y + aZ1)));
                        const float n0 = tanhf(gn.x + r0 * (aN0 + bn2.x));
                        const float n1 = tanhf(gn.y + r1 * (aN1 + bn2.y));
                        float2 o;
                        o.x = (1.f - z0) * n0 + z0 * hp.x;
                        o.y = (1.f - z1) * n1 + z1 * hp.y;
                        *(float2*)(out + (size_t)item * H_DIM + j) = o;
                    }
                }
            }
        }

        off += n;
        grid_barrier(sense);
    }
}

// ---------------------------------------------------------------------------
extern "C" void kernel_launch(void* const* d_in, const int* in_sizes, int n_in,
                              void* d_out, int out_size) {
    const float* ins    = (const float*)d_in[0];   // [T,B,H]
    const int*   resets = (const int*)d_in[1];     // [T,B] int32 (bool promoted)
    const float* carry  = (const float*)d_in[2];   // [B,H]
    const float* Wi     = (const float*)d_in[3];   // [H,3H]
    const float* bi     = (const float*)d_in[4];   // [3H]
    const float* Wh     = (const float*)d_in[5];   // [H,3H]
    const float* bhn    = (const float*)d_in[6];   // [H]
    float*       out    = (float*)d_out;           // [T,B,H]

    static bool attr_done = false;
    if (!attr_done) {
        cudaFuncSetAttribute(gi_gemm, cudaFuncAttributeMaxDynamicSharedMemorySize, GI_SMEM_BYTES);
        cudaFuncSetAttribute(gru_waves, cudaFuncAttributeMaxDynamicSharedMemorySize, WV_SMEM_BYTES);
        attr_done = true;
    }

    // Phase 0: weight convert (Wi fp16, Wh fp16 hi/lo)
    w_split<<<768, 256>>>(Wi, Wh);

    // Phase 1: input gates (single-term fp16) + concurrent schedule build
    dim3 g1(H3 / 128, M_TOT / 128 + 1);
    gi_gemm<<<g1, 256, GI_SMEM_BYTES>>>(ins, bi, resets);

    // Phase 2: all reset rows — pure pointwise, no GEMM, no dependencies
    flat_reset<<<1184, 256>>>(bhn, out);

    // Phase 3: dependency waves (non-reset rows only) — persistent, 2 CTAs/SM
    gru_waves<<<NCTA2, 256, WV_SMEM_BYTES>>>(carry, bhn, out);
}